// round 11
// baseline (speedup 1.0000x reference)
#include <cuda_runtime.h>

#define BH 16
#define NSEQ 2048
#define DD 32
#define MM 64
#define LL 32
#define CC (NSEQ/LL)   // 64 chunks
#define NBLK 512       // BH * 32 superblocks (2 chunks each)

typedef unsigned long long u64;

// packed f32x2 helpers
__device__ __forceinline__ u64 pk2(float x, float y) {
    u64 r; asm("mov.b64 %0, {%1, %2};" : "=l"(r) : "f"(x), "f"(y)); return r;
}
__device__ __forceinline__ void fma2(u64& d, u64 a, u64 b) {
    asm("fma.rn.f32x2 %0, %1, %2, %0;" : "+l"(d) : "l"(a), "l"(b));
}
__device__ __forceinline__ float2 up2(u64 a) {
    float2 f; asm("mov.b64 {%0, %1}, %2;" : "=f"(f.x), "=f"(f.y) : "l"(a)); return f;
}

#define LN_SQRT_M 2.0794415416798357f   // ln(8): folds 1/sqrt(64) into exp

// Scratch (device globals)
__device__ float g_skv[BH*CC*MM*DD];      // 8 MB: chunk KV sums -> exclusive prefix
__device__ float g_sk [BH*CC*MM];         // 256 KB
// grid barrier state (epoch monotonic across graph replays; cnt self-resets)
__device__ unsigned int g_bar_cnt = 0;
__device__ unsigned int g_bar_epoch = 0;

__device__ __forceinline__ void grid_barrier()
{
    __syncthreads();
    if (threadIdx.x == 0) {
        __threadfence();
        unsigned int e = *((volatile unsigned int*)&g_bar_epoch);
        unsigned int old = atomicAdd(&g_bar_cnt, 1);
        if (old == NBLK - 1) {
            g_bar_cnt = 0;
            __threadfence();
            *((volatile unsigned int*)&g_bar_epoch) = e + 1;
        } else {
            while (*((volatile unsigned int*)&g_bar_epoch) == e) { __nanosleep(64); }
        }
        __threadfence();
    }
    __syncthreads();
}

// ---------------------------------------------------------------------------
// ONE persistent kernel: phi -> chunk sums -> [grid bar] -> scan -> [grid bar]
// -> per-chunk output. phi_q/phi_k never touch global memory.
// smem = 48KB/CTA, launch_bounds(256,4) => 4 CTA/SM => 592 slots >= 512 blocks.
// ---------------------------------------------------------------------------
__global__ void __launch_bounds__(256, 4) fused_kernel(
    const float* __restrict__ q, const float* __restrict__ k,
    const float* __restrict__ v, const float* __restrict__ omega,
    float* __restrict__ out)
{
    __shared__ float s_om[DD*MM];    // 8KB: omega [d][m]; later A_p/kp/den
    __shared__ float s_x [64*DD];    // 8KB: q/k halves in phi; later v [t][d]
    __shared__ float pk_s[64*MM];    // 16KB: phi_k [t][m]; rows 0-31 later Sp
    __shared__ float pq_s[64*MM];    // 16KB: phi_q [t][logical-f4 swizzled]

    int tid = threadIdx.x;
    int blk = blockIdx.x;                    // bh*32 + cc2
    int bh  = blk >> 5;
    int cc2 = blk & 31;
    int base_tok = bh*NSEQ + cc2*64;

    // omega[m][d] -> s_om[d][m], conflict-free stores
    {
        int m = tid & 63;
        int d0 = (tid >> 6) * 8;
        #pragma unroll
        for (int jj = 0; jj < 8; jj++) {
            int d = d0 + jj;
            s_om[d*MM + m] = omega[m*DD + d];
        }
    }

    // ===================== PHI (two d-half passes) =====================
    int tp = tid >> 3;           // 0..31 token pair
    int mg = tid & 7;            // m groups
    int t0 = tp*2, t1 = t0+1;
    u64 Aq0[4] = {0,0,0,0}, Aq1[4] = {0,0,0,0};
    u64 Ak0[4] = {0,0,0,0}, Ak1[4] = {0,0,0,0};
    float nq0=0.f, nq1=0.f, nk0=0.f, nk1=0.f;

    #pragma unroll
    for (int p = 0; p < 2; p++) {
        // load 16-d halves of q,k for 64 tokens (4KB each)
        {
            int t = tid >> 2, f = tid & 3;
            const float4* qrow = (const float4*)(q + (base_tok + t)*DD + p*16);
            const float4* krow = (const float4*)(k + (base_tok + t)*DD + p*16);
            ((float4*)s_x)[t*4 + f]       = qrow[f];
            ((float4*)s_x)[256 + t*4 + f] = krow[f];
        }
        __syncthreads();
        const float4* xq4 = (const float4*)s_x;          // [t*4 + dc]
        const float4* xk4 = ((const float4*)s_x) + 256;
        const ulonglong2* omu = (const ulonglong2*)s_om; // 16 per d-row
        #pragma unroll
        for (int dc = 0; dc < 4; dc++) {
            float4 xq0 = xq4[t0*4 + dc], xq1 = xq4[t1*4 + dc];
            float4 xk0 = xk4[t0*4 + dc], xk1 = xk4[t1*4 + dc];
            float q0l[4] = {xq0.x, xq0.y, xq0.z, xq0.w};
            float q1l[4] = {xq1.x, xq1.y, xq1.z, xq1.w};
            float k0l[4] = {xk0.x, xk0.y, xk0.z, xk0.w};
            float k1l[4] = {xk1.x, xk1.y, xk1.z, xk1.w};
            #pragma unroll
            for (int dd = 0; dd < 4; dd++) {
                int d = p*16 + dc*4 + dd;
                ulonglong2 o0 = omu[d*16 + mg];
                ulonglong2 o1 = omu[d*16 + 8 + mg];
                float a = q0l[dd], b = q1l[dd], c = k0l[dd], e = k1l[dd];
                u64 aa = pk2(a,a), bb = pk2(b,b), cc = pk2(c,c), ee = pk2(e,e);
                fma2(Aq0[0], aa, o0.x); fma2(Aq0[1], aa, o0.y);
                fma2(Aq0[2], aa, o1.x); fma2(Aq0[3], aa, o1.y);
                fma2(Aq1[0], bb, o0.x); fma2(Aq1[1], bb, o0.y);
                fma2(Aq1[2], bb, o1.x); fma2(Aq1[3], bb, o1.y);
                fma2(Ak0[0], cc, o0.x); fma2(Ak0[1], cc, o0.y);
                fma2(Ak0[2], cc, o1.x); fma2(Ak0[3], cc, o1.y);
                fma2(Ak1[0], ee, o0.x); fma2(Ak1[1], ee, o0.y);
                fma2(Ak1[2], ee, o1.x); fma2(Ak1[3], ee, o1.y);
                nq0 += a*a; nq1 += b*b; nk0 += c*c; nk1 += e*e;
            }
        }
        __syncthreads();
    }
    nq0 = nq0*0.5f + LN_SQRT_M; nq1 = nq1*0.5f + LN_SQRT_M;
    nk0 = nk0*0.5f + LN_SQRT_M; nk1 = nk1*0.5f + LN_SQRT_M;

    // phi_q -> pq_s with f4-group XOR swizzle (group g at position g^(t&7) in
    // each 8-group half); phi_k -> pk_s plain. No global stores.
    #define EXPST(ACC, n, tok, ISK) { \
        float2 e0 = up2(ACC[0]), e1 = up2(ACC[1]); \
        float2 e2 = up2(ACC[2]), e3 = up2(ACC[3]); \
        float4 plo, phv; \
        plo.x = __expf(e0.x - n); plo.y = __expf(e0.y - n); \
        plo.z = __expf(e1.x - n); plo.w = __expf(e1.y - n); \
        phv.x = __expf(e2.x - n); phv.y = __expf(e2.y - n); \
        phv.z = __expf(e3.x - n); phv.w = __expf(e3.y - n); \
        if (ISK) { \
            *(float4*)&pk_s[(tok)*MM + mg*4]      = plo; \
            *(float4*)&pk_s[(tok)*MM + 32 + mg*4] = phv; \
        } else { \
            *(float4*)&pq_s[(tok)*MM + (mg ^ ((tok)&7))*4]        = plo; \
            *(float4*)&pq_s[(tok)*MM + (8 + (mg ^ ((tok)&7)))*4]  = phv; \
        } }
    EXPST(Aq0, nq0, t0, 0)
    EXPST(Aq1, nq1, t1, 0)
    EXPST(Ak0, nk0, t0, 1)
    EXPST(Ak1, nk1, t1, 1)
    #undef EXPST
    __syncthreads();

    // load v (full 64 tokens) into s_x
    {
        const float4* v4 = (const float4*)(v + base_tok*DD);
        ((float4*)s_x)[tid]       = v4[tid];
        ((float4*)s_x)[tid + 256] = v4[tid + 256];
    }
    __syncthreads();

    // ===================== CHUNK SUMS =====================
    {
        int ch = tid >> 7;           // chunk 0/1
        int r  = tid & 127;
        int m  = r >> 1;
        int dh = r & 1;
        const ulonglong2* vsu = (const ulonglong2*)s_x;
        const float* pk = &pk_s[ch*32*MM];
        u64 A[8] = {0,0,0,0,0,0,0,0};
        float ks = 0.f;
        #pragma unroll 8
        for (int t = 0; t < LL; t++) {
            float p = pk[t*MM + m];
            u64 pp = pk2(p, p);
            ulonglong2 w0 = vsu[(ch*32+t)*8 + dh*4 + 0];
            ulonglong2 w1 = vsu[(ch*32+t)*8 + dh*4 + 1];
            ulonglong2 w2 = vsu[(ch*32+t)*8 + dh*4 + 2];
            ulonglong2 w3 = vsu[(ch*32+t)*8 + dh*4 + 3];
            fma2(A[0], pp, w0.x); fma2(A[1], pp, w0.y);
            fma2(A[2], pp, w1.x); fma2(A[3], pp, w1.y);
            fma2(A[4], pp, w2.x); fma2(A[5], pp, w2.y);
            fma2(A[6], pp, w3.x); fma2(A[7], pp, w3.y);
            ks += p;
        }
        int blkc = bh*CC + cc2*2 + ch;
        ulonglong2* skvU = (ulonglong2*)g_skv + (size_t)(blkc*MM + m)*8 + dh*4;
        ulonglong2 s;
        s.x = A[0]; s.y = A[1]; skvU[0] = s;
        s.x = A[2]; s.y = A[3]; skvU[1] = s;
        s.x = A[4]; s.y = A[5]; skvU[2] = s;
        s.x = A[6]; s.y = A[7]; skvU[3] = s;
        if (dh == 0) g_sk[blkc*MM + m] = ks;
    }

    grid_barrier();

    // ===================== SCAN (blocks 0..35) =====================
    {
        int idx = blk*256 + tid;
        const int NSKV = BH*MM*8;
        if (idx < NSKV) {
            int sbh = idx / (MM*8);
            int r   = idx % (MM*8);
            float4* base = (float4*)g_skv + (size_t)sbh*CC*MM*8 + r;
            float4 run = {0,0,0,0};
            #pragma unroll 8
            for (int c = 0; c < CC; c++) {
                float4 t = base[(size_t)c*MM*8];
                base[(size_t)c*MM*8] = run;
                run.x += t.x; run.y += t.y; run.z += t.z; run.w += t.w;
            }
        } else if (idx < NSKV + BH*MM) {
            int j   = idx - NSKV;
            int sbh = j / MM, m = j % MM;
            float* base = g_sk + sbh*CC*MM + m;
            float run = 0.f;
            #pragma unroll 8
            for (int c = 0; c < CC; c++) {
                float t = base[c*MM];
                base[c*MM] = run;
                run += t;
            }
        }
    }

    grid_barrier();

    // ===================== OUTPUT (2 chunks sequentially) =====================
    float* s_A   = s_om;          // [i][j] stride 33, 4224B
    float* s_kp  = s_om + 1056;   // 64 floats
    float* s_den = s_om + 1120;   // 32 floats

    #pragma unroll
    for (int ch = 0; ch < 2; ch++) {
        int blkc = bh*CC + cc2*2 + ch;

        // prefetch Sp into registers (hidden under Phase A)
        const float4* gs4 = (const float4*)&g_skv[(size_t)blkc*MM*DD];
        float4 sp_r0 = gs4[tid];
        float4 sp_r1 = gs4[tid + 256];

        if (tid < MM) s_kp[tid] = g_sk[blkc*MM + tid];
        if (tid < LL) s_den[tid] = 1e-6f;
        __syncthreads();

        // --- Phase A: i = lane, warp w owns j = w*4..w*4+3 ---
        {
            int i = tid & 31;
            int w = tid >> 5;
            int j0 = w * 4;
            int t = ch*32 + i;
            int sw = i & 7;
            const ulonglong2* pqU = (const ulonglong2*)pq_s;
            const ulonglong2* pkU = (const ulonglong2*)pk_s;
            const ulonglong2* kpU = (const ulonglong2*)s_kp;
            u64 D0=0, D1=0, D2=0, D3=0, QK=0;
            #pragma unroll
            for (int m4 = 0; m4 < 16; m4++) {
                int qs = (m4 < 8) ? (m4 ^ sw) : (8 + ((m4-8) ^ sw));
                ulonglong2 qv = pqU[t*16 + qs];
                ulonglong2 k0 = pkU[(ch*32+j0+0)*16 + m4];
                ulonglong2 k1 = pkU[(ch*32+j0+1)*16 + m4];
                ulonglong2 k2 = pkU[(ch*32+j0+2)*16 + m4];
                ulonglong2 k3 = pkU[(ch*32+j0+3)*16 + m4];
                ulonglong2 kv = kpU[m4];
                fma2(D0, qv.x, k0.x); fma2(D0, qv.y, k0.y);
                fma2(D1, qv.x, k1.x); fma2(D1, qv.y, k1.y);
                fma2(D2, qv.x, k2.x); fma2(D2, qv.y, k2.y);
                fma2(D3, qv.x, k3.x); fma2(D3, qv.y, k3.y);
                fma2(QK, qv.x, kv.x); fma2(QK, qv.y, kv.y);
            }
            float2 f0=up2(D0), f1=up2(D1), f2=up2(D2), f3=up2(D3), fq=up2(QK);
            float a0 = f0.x+f0.y, a1 = f1.x+f1.y;
            float a2 = f2.x+f2.y, a3 = f3.x+f3.y;
            float qk = fq.x+fq.y;
            if (j0+0 > i) a0 = 0.f;
            if (j0+1 > i) a1 = 0.f;
            if (j0+2 > i) a2 = 0.f;
            if (j0+3 > i) a3 = 0.f;
            s_A[i*33 + j0+0] = a0;
            s_A[i*33 + j0+1] = a1;
            s_A[i*33 + j0+2] = a2;
            s_A[i*33 + j0+3] = a3;
            float dpart = a0 + a1 + a2 + a3 + (w == 0 ? qk : 0.f);
            atomicAdd(&s_den[i], dpart);
        }
        __syncthreads();

        // park Sp in pk_s rows 0..31 (dead after this chunk's Phase A for ch=0;
        // for ch=1 Phase A used rows 32..63, so rows 0..31 free again)
        ((float4*)pk_s)[tid]       = sp_r0;
        ((float4*)pk_s)[tid + 256] = sp_r1;
        __syncthreads();

        // --- Phase B ---
        {
            int i = tid >> 3;
            int g = tid & 7;
            int t = ch*32 + i;
            int sw = i & 7;
            const float4* pq4 = (const float4*)pq_s;
            const ulonglong2* SpU = (const ulonglong2*)pk_s;
            const ulonglong2* vsU = (const ulonglong2*)s_x;
            u64 O0 = 0, O1 = 0;
            #pragma unroll
            for (int m4 = 0; m4 < 16; m4++) {
                int qs = (m4 < 8) ? (m4 ^ sw) : (8 + ((m4-8) ^ sw));
                float4 qv = pq4[t*16 + qs];
                ulonglong2 s0 = SpU[(m4*4+0)*8 + g];
                ulonglong2 s1 = SpU[(m4*4+1)*8 + g];
                ulonglong2 s2 = SpU[(m4*4+2)*8 + g];
                ulonglong2 s3 = SpU[(m4*4+3)*8 + g];
                u64 tt;
                tt = pk2(qv.x, qv.x); fma2(O0, tt, s0.x); fma2(O1, tt, s0.y);
                tt = pk2(qv.y, qv.y); fma2(O0, tt, s1.x); fma2(O1, tt, s1.y);
                tt = pk2(qv.z, qv.z); fma2(O0, tt, s2.x); fma2(O1, tt, s2.y);
                tt = pk2(qv.w, qv.w); fma2(O0, tt, s3.x); fma2(O1, tt, s3.y);
            }
            #pragma unroll
            for (int j = 0; j < LL; j++) {
                float a = s_A[i*33 + j];
                u64 aa = pk2(a, a);
                ulonglong2 vv = vsU[(ch*32+j)*8 + g];
                fma2(O0, aa, vv.x); fma2(O1, aa, vv.y);
            }
            float dinv = 1.0f / s_den[i];
            float2 o01 = up2(O0), o23 = up2(O1);
            float4* o4 = (float4*)&out[(base_tok + ch*32 + i)*DD + g*4];
            *o4 = make_float4(o01.x*dinv, o01.y*dinv, o23.x*dinv, o23.y*dinv);
        }
        __syncthreads();
    }
}

// ---------------------------------------------------------------------------
extern "C" void kernel_launch(void* const* d_in, const int* in_sizes, int n_in,
                              void* d_out, int out_size)
{
    const float* q     = (const float*)d_in[0];
    const float* k     = (const float*)d_in[1];
    const float* v     = (const float*)d_in[2];
    const float* omega = (const float*)d_in[3];
    float* out = (float*)d_out;

    fused_kernel<<<NBLK, 256>>>(q, k, v, omega, out);
}

// round 12
// speedup vs baseline: 1.0672x; 1.0672x over previous
#include <cuda_runtime.h>

#define BH 16
#define NSEQ 2048
#define DD 32
#define MM 64
#define LL 32
#define CC (NSEQ/LL)   // 64 chunks

typedef unsigned long long u64;

// packed f32x2 helpers (Blackwell FFMA2: ptxas never auto-fuses; PTX-only)
__device__ __forceinline__ u64 pk2(float x, float y) {
    u64 r; asm("mov.b64 %0, {%1, %2};" : "=l"(r) : "f"(x), "f"(y)); return r;
}
__device__ __forceinline__ void fma2(u64& d, u64 a, u64 b) {
    asm("fma.rn.f32x2 %0, %1, %2, %0;" : "+l"(d) : "l"(a), "l"(b));
}
__device__ __forceinline__ float2 up2(u64 a) {
    float2 f; asm("mov.b64 {%0, %1}, %2;" : "=f"(f.x), "=f"(f.y) : "l"(a)); return f;
}

#define LN_SQRT_M 2.0794415416798357f   // ln(8): folds the 1/sqrt(64) factor

// Scratch (device globals: no allocation allowed in kernel_launch)
__device__ float g_phi_q[BH*NSEQ*MM];     // 8 MB
__device__ float g_phi_k[BH*NSEQ*MM];     // 8 MB
__device__ float g_skv[BH*CC*MM*DD];      // 8 MB  (chunk KV sums -> exclusive prefix)
__device__ float g_sk [BH*CC*MM];         // 256 KB

// ---------------------------------------------------------------------------
// Kernel 1 (fused): per block = 2 chunks (64 tokens), 256 threads. (R10 known-good)
// ---------------------------------------------------------------------------
__global__ void __launch_bounds__(256, 4) phi_sum_kernel(
    const float* __restrict__ q, const float* __restrict__ k,
    const float* __restrict__ v, const float* __restrict__ omega)
{
    __shared__ float om_t[DD*MM];    // [d][m] transposed, 8 KB
    __shared__ float xq[64*DD];      // 8 KB (reused for v in phase 2)
    __shared__ float xk[64*DD];      // 8 KB
    __shared__ float pk_s[64*MM];    // [t][m] 16 KB

    int tid = threadIdx.x;
    int blk = blockIdx.x;                    // bh*32 + cc2
    int bh  = blk >> 5;
    int cc2 = blk & 31;                      // superblock of 2 chunks
    int base_tok = bh*NSEQ + cc2*64;

    // omega[m][d] -> om_t[d][m], conflict-free stores
    {
        int m = tid & 63;
        int d0 = (tid >> 6) * 8;
        #pragma unroll
        for (int jj = 0; jj < 8; jj++) {
            int d = d0 + jj;
            om_t[d*MM + m] = omega[m*DD + d];
        }
    }
    // load 64 tokens of q,k (512 float4 each)
    {
        const float4* q4 = (const float4*)(q + base_tok*DD);
        const float4* k4 = (const float4*)(k + base_tok*DD);
        ((float4*)xq)[tid]       = q4[tid];
        ((float4*)xq)[tid + 256] = q4[tid + 256];
        ((float4*)xk)[tid]       = k4[tid];
        ((float4*)xk)[tid + 256] = k4[tid + 256];
    }
    __syncthreads();

    // --- phi phase: packed FFMA2 accumulation ---
    {
        int tp = tid >> 3;           // 0..31 token pair
        int mg = tid & 7;            // m groups {mg*4..+3} and {32+mg*4..+3}
        int t0 = tp*2, t1 = t0+1;
        const ulonglong2* omu = (const ulonglong2*)om_t;  // 16 per d-row
        const float4* xq4 = (const float4*)xq;            // 8 f4 per token
        const float4* xk4 = (const float4*)xk;

        u64 Aq0[4] = {0,0,0,0}, Aq1[4] = {0,0,0,0};
        u64 Ak0[4] = {0,0,0,0}, Ak1[4] = {0,0,0,0};
        float nq0=0.f, nq1=0.f, nk0=0.f, nk1=0.f;

        #pragma unroll
        for (int dc = 0; dc < 8; dc++) {          // 4 d's per iter
            float4 xq0 = xq4[t0*8 + dc], xq1 = xq4[t1*8 + dc];
            float4 xk0 = xk4[t0*8 + dc], xk1 = xk4[t1*8 + dc];
            float q0l[4] = {xq0.x, xq0.y, xq0.z, xq0.w};
            float q1l[4] = {xq1.x, xq1.y, xq1.z, xq1.w};
            float k0l[4] = {xk0.x, xk0.y, xk0.z, xk0.w};
            float k1l[4] = {xk1.x, xk1.y, xk1.z, xk1.w};
            #pragma unroll
            for (int dd = 0; dd < 4; dd++) {
                int d = dc*4 + dd;
                ulonglong2 o0 = omu[d*16 + mg];       // quarter-warp broadcast
                ulonglong2 o1 = omu[d*16 + 8 + mg];
                float a = q0l[dd], b = q1l[dd], c = k0l[dd], e = k1l[dd];
                u64 aa = pk2(a,a), bb = pk2(b,b), cc = pk2(c,c), ee = pk2(e,e);
                fma2(Aq0[0], aa, o0.x); fma2(Aq0[1], aa, o0.y);
                fma2(Aq0[2], aa, o1.x); fma2(Aq0[3], aa, o1.y);
                fma2(Aq1[0], bb, o0.x); fma2(Aq1[1], bb, o0.y);
                fma2(Aq1[2], bb, o1.x); fma2(Aq1[3], bb, o1.y);
                fma2(Ak0[0], cc, o0.x); fma2(Ak0[1], cc, o0.y);
                fma2(Ak0[2], cc, o1.x); fma2(Ak0[3], cc, o1.y);
                fma2(Ak1[0], ee, o0.x); fma2(Ak1[1], ee, o0.y);
                fma2(Ak1[2], ee, o1.x); fma2(Ak1[3], ee, o1.y);
                nq0 += a*a; nq1 += b*b; nk0 += c*c; nk1 += e*e;
            }
        }
        nq0 = nq0*0.5f + LN_SQRT_M; nq1 = nq1*0.5f + LN_SQRT_M;
        nk0 = nk0*0.5f + LN_SQRT_M; nk1 = nk1*0.5f + LN_SQRT_M;

        #define EXPST(ACC, n, tok, PKS) { \
            float2 e0 = up2(ACC[0]), e1 = up2(ACC[1]); \
            float2 e2 = up2(ACC[2]), e3 = up2(ACC[3]); \
            float4 plo, phv; \
            plo.x = __expf(e0.x - n); plo.y = __expf(e0.y - n); \
            plo.z = __expf(e1.x - n); plo.w = __expf(e1.y - n); \
            phv.x = __expf(e2.x - n); phv.y = __expf(e2.y - n); \
            phv.z = __expf(e3.x - n); phv.w = __expf(e3.y - n); \
            if (PKS) { \
                *(float4*)&g_phi_k[(base_tok+tok)*MM + mg*4]      = plo; \
                *(float4*)&g_phi_k[(base_tok+tok)*MM + 32 + mg*4] = phv; \
                *(float4*)&pk_s[(tok)*MM + mg*4]      = plo; \
                *(float4*)&pk_s[(tok)*MM + 32 + mg*4] = phv; \
            } else { \
                *(float4*)&g_phi_q[(base_tok+tok)*MM + mg*4]      = plo; \
                *(float4*)&g_phi_q[(base_tok+tok)*MM + 32 + mg*4] = phv; \
            } }
        EXPST(Aq0, nq0, t0, 0)
        EXPST(Aq1, nq1, t1, 0)
        EXPST(Ak0, nk0, t0, 1)
        EXPST(Ak1, nk1, t1, 1)
        #undef EXPST
    }
    __syncthreads();

    // load v into xq buffer (q dead)
    {
        const float4* v4 = (const float4*)(v + base_tok*DD);
        ((float4*)xq)[tid]       = v4[tid];
        ((float4*)xq)[tid + 256] = v4[tid + 256];
    }
    __syncthreads();

    // --- chunk sums (packed): 128 threads per chunk; thread = (m, d-half) ---
    {
        int ch = tid >> 7;           // chunk 0/1
        int r  = tid & 127;
        int m  = r >> 1;             // 0..63
        int dh = r & 1;              // d half (16 d's = 4 ull2)
        const ulonglong2* vsu = (const ulonglong2*)xq;
        const float* pk = &pk_s[ch*32*MM];
        u64 A[8] = {0,0,0,0,0,0,0,0};
        float ks = 0.f;
        #pragma unroll 8
        for (int t = 0; t < LL; t++) {
            float p = pk[t*MM + m];
            u64 pp = pk2(p, p);
            ulonglong2 w0 = vsu[(ch*32+t)*8 + dh*4 + 0];
            ulonglong2 w1 = vsu[(ch*32+t)*8 + dh*4 + 1];
            ulonglong2 w2 = vsu[(ch*32+t)*8 + dh*4 + 2];
            ulonglong2 w3 = vsu[(ch*32+t)*8 + dh*4 + 3];
            fma2(A[0], pp, w0.x); fma2(A[1], pp, w0.y);
            fma2(A[2], pp, w1.x); fma2(A[3], pp, w1.y);
            fma2(A[4], pp, w2.x); fma2(A[5], pp, w2.y);
            fma2(A[6], pp, w3.x); fma2(A[7], pp, w3.y);
            ks += p;
        }
        int blkc = bh*CC + cc2*2 + ch;
        ulonglong2* skvU = (ulonglong2*)g_skv + (size_t)(blkc*MM + m)*8 + dh*4;
        ulonglong2 s;
        s.x = A[0]; s.y = A[1]; skvU[0] = s;
        s.x = A[2]; s.y = A[3]; skvU[1] = s;
        s.x = A[4]; s.y = A[5]; skvU[2] = s;
        s.x = A[6]; s.y = A[7]; skvU[3] = s;
        if (dh == 0) g_sk[blkc*MM + m] = ks;
    }
}

// ---------------------------------------------------------------------------
// Kernel 2: exclusive prefix scan over chunks (in place), float4 for skv.
// ---------------------------------------------------------------------------
__global__ void scan_kernel()
{
    int idx = blockIdx.x * blockDim.x + threadIdx.x;
    const int NSKV = BH*MM*8;        // float4 series
    if (idx < NSKV) {
        int bh = idx / (MM*8);
        int r  = idx % (MM*8);       // m*8 + d4
        float4* base = (float4*)g_skv + (size_t)bh*CC*MM*8 + r;
        float4 run = {0,0,0,0};
        #pragma unroll 4
        for (int c = 0; c < CC; c++) {
            float4 t = base[(size_t)c*MM*8];
            base[(size_t)c*MM*8] = run;
            run.x += t.x; run.y += t.y; run.z += t.z; run.w += t.w;
        }
    } else if (idx < NSKV + BH*MM) {
        int j  = idx - NSKV;
        int bh = j / MM, m = j % MM;
        float* base = g_sk + bh*CC*MM + m;
        float run = 0.f;
        #pragma unroll 4
        for (int c = 0; c < CC; c++) {
            float t = base[c*MM];
            base[c*MM] = run;
            run += t;
        }
    }
}

// ---------------------------------------------------------------------------
// Kernel 3: per-(bh,chunk) output.
//  - NO den atomics: Phase A stores qk term to s_qk (single warp, plain ST);
//    rowsum(A) folded into Phase B's A@v loop (A values already broadcast there)
//  - Phase B j-loop is triangular: bound (i|3) is warp-uniform
// ---------------------------------------------------------------------------
__global__ void __launch_bounds__(256) out_kernel(
    const float* __restrict__ v, float* __restrict__ out)
{
    __shared__ float pq_p[LL*68];    // [i][m], row stride 17 f4, 8.5 KB
    __shared__ float buf [MM*DD];    // pk [j][m] in A, then Sp [m][d] in B
    __shared__ float vs  [LL*DD];
    __shared__ float A_p [LL*33];    // [i][j], row stride 33 (masked entries = 0)
    __shared__ float kp  [MM];
    __shared__ float s_qk[LL];       // phi_q[i] . kp

    int tid = threadIdx.x;
    int blk = blockIdx.x;
    int base_tok = (blk/CC)*NSEQ + (blk%CC)*LL;

    // Early Sp loads -> registers (consumed after Phase A)
    const float4* gs4 = (const float4*)&g_skv[(size_t)blk*MM*DD];
    float4 sp_r0 = gs4[tid];
    float4 sp_r1 = gs4[tid + 256];

    {
        const float4* gq4 = (const float4*)&g_phi_q[base_tok*MM];
        const float4* gk4 = (const float4*)&g_phi_k[base_tok*MM];
        const float4* gv4 = (const float4*)(v + base_tok*DD);
        float4* pq4w = (float4*)pq_p;
        #pragma unroll
        for (int r = 0; r < 2; r++) {
            int idx = tid + r*256;               // i*16 + m4
            int i = idx >> 4, m4 = idx & 15;
            pq4w[i*17 + m4] = gq4[idx];
            ((float4*)buf)[idx] = gk4[idx];      // pk [j][m]
        }
        ((float4*)vs)[tid] = gv4[tid];
        if (tid < MM) kp[tid] = g_sk[blk*MM + tid];
    }
    __syncthreads();

    // --- Phase A: i = lane, warp w owns j = w*4 .. w*4+3; packed dots ---
    {
        int i = tid & 31;
        int w = tid >> 5;
        int j0 = w * 4;
        const ulonglong2* pqU = (const ulonglong2*)pq_p;
        const ulonglong2* pkU = (const ulonglong2*)buf;
        const ulonglong2* kpU = (const ulonglong2*)kp;
        u64 D0=0, D1=0, D2=0, D3=0, QK=0;
        #pragma unroll
        for (int m4 = 0; m4 < 16; m4++) {
            ulonglong2 qv = pqU[i*17 + m4];
            ulonglong2 k0 = pkU[(j0+0)*16 + m4];
            ulonglong2 k1 = pkU[(j0+1)*16 + m4];
            ulonglong2 k2 = pkU[(j0+2)*16 + m4];
            ulonglong2 k3 = pkU[(j0+3)*16 + m4];
            fma2(D0, qv.x, k0.x); fma2(D0, qv.y, k0.y);
            fma2(D1, qv.x, k1.x); fma2(D1, qv.y, k1.y);
            fma2(D2, qv.x, k2.x); fma2(D2, qv.y, k2.y);
            fma2(D3, qv.x, k3.x); fma2(D3, qv.y, k3.y);
            if (w == 0) {
                ulonglong2 kv = kpU[m4];
                fma2(QK, qv.x, kv.x); fma2(QK, qv.y, kv.y);
            }
        }
        float2 f0 = up2(D0), f1 = up2(D1), f2 = up2(D2), f3 = up2(D3);
        float a0 = f0.x + f0.y, a1 = f1.x + f1.y;
        float a2 = f2.x + f2.y, a3 = f3.x + f3.y;
        if (j0+0 > i) a0 = 0.f;
        if (j0+1 > i) a1 = 0.f;
        if (j0+2 > i) a2 = 0.f;
        if (j0+3 > i) a3 = 0.f;
        A_p[i*33 + j0+0] = a0;
        A_p[i*33 + j0+1] = a1;
        A_p[i*33 + j0+2] = a2;
        A_p[i*33 + j0+3] = a3;
        if (w == 0) {
            float2 fq = up2(QK);
            s_qk[i] = fq.x + fq.y + 1e-6f;
        }
    }
    __syncthreads();

    // pk dead: store prefetched Sp registers into buf
    ((float4*)buf)[tid]       = sp_r0;
    ((float4*)buf)[tid + 256] = sp_r1;
    __syncthreads();

    // --- Phase B (packed, triangular j-loop, inline den) ---
    {
        int i = tid >> 3;
        int g = tid & 7;
        const float4* pq4 = (const float4*)pq_p;
        const ulonglong2* SpU = (const ulonglong2*)buf;
        const ulonglong2* vsU = (const ulonglong2*)vs;
        u64 O0 = 0, O1 = 0;     // {o.x,o.y}, {o.z,o.w}
        #pragma unroll
        for (int m4 = 0; m4 < 16; m4++) {
            float4 qv = pq4[i*17 + m4];
            ulonglong2 s0 = SpU[(m4*4+0)*8 + g];
            ulonglong2 s1 = SpU[(m4*4+1)*8 + g];
            ulonglong2 s2 = SpU[(m4*4+2)*8 + g];
            ulonglong2 s3 = SpU[(m4*4+3)*8 + g];
            u64 t;
            t = pk2(qv.x, qv.x); fma2(O0, t, s0.x); fma2(O1, t, s0.y);
            t = pk2(qv.y, qv.y); fma2(O0, t, s1.x); fma2(O1, t, s1.y);
            t = pk2(qv.z, qv.z); fma2(O0, t, s2.x); fma2(O1, t, s2.y);
            t = pk2(qv.w, qv.w); fma2(O0, t, s3.x); fma2(O1, t, s3.y);
        }
        // Triangular A@v: bound (i|3) is identical across the warp
        int jmax = i | 3;              // >= i; A entries beyond i are stored 0
        float den = s_qk[i];           // includes +1e-6
        for (int j = 0; j <= jmax; j++) {
            float a = A_p[i*33 + j];
            den += a;                  // masked entries contribute 0
            u64 aa = pk2(a, a);
            ulonglong2 vv = vsU[j*8 + g];
            fma2(O0, aa, vv.x); fma2(O1, aa, vv.y);
        }
        float dinv = 1.0f / den;
        float2 o01 = up2(O0), o23 = up2(O1);
        float4* o4 = (float4*)&out[(base_tok + i)*DD + g*4];
        *o4 = make_float4(o01.x*dinv, o01.y*dinv, o23.x*dinv, o23.y*dinv);
    }
}

// ---------------------------------------------------------------------------
extern "C" void kernel_launch(void* const* d_in, const int* in_sizes, int n_in,
                              void* d_out, int out_size)
{
    const float* q     = (const float*)d_in[0];
    const float* k     = (const float*)d_in[1];
    const float* v     = (const float*)d_in[2];
    const float* omega = (const float*)d_in[3];
    float* out = (float*)d_out;

    phi_sum_kernel<<<BH*CC/2, 256>>>(q, k, v, omega);
    const int scan_threads = BH*MM*8 + BH*MM;
    scan_kernel<<<(scan_threads + 255)/256, 256>>>();
    out_kernel<<<BH*CC, 256>>>(v, out);
}

// round 13
// speedup vs baseline: 1.1148x; 1.0446x over previous
#include <cuda_runtime.h>

#define BH 16
#define NSEQ 2048
#define DD 32
#define MM 64
#define LL 32
#define CC (NSEQ/LL)   // 64 chunks

typedef unsigned long long u64;

// packed f32x2 helpers (Blackwell FFMA2: ptxas never auto-fuses; PTX-only)
__device__ __forceinline__ u64 pk2(float x, float y) {
    u64 r; asm("mov.b64 %0, {%1, %2};" : "=l"(r) : "f"(x), "f"(y)); return r;
}
__device__ __forceinline__ void fma2(u64& d, u64 a, u64 b) {
    asm("fma.rn.f32x2 %0, %1, %2, %0;" : "+l"(d) : "l"(a), "l"(b));
}
__device__ __forceinline__ float2 up2(u64 a) {
    float2 f; asm("mov.b64 {%0, %1}, %2;" : "=f"(f.x), "=f"(f.y) : "l"(a)); return f;
}

#define LN_SQRT_M 2.0794415416798357f   // ln(8): folds the 1/sqrt(64) factor

// Scratch (device globals: no allocation allowed in kernel_launch)
__device__ float g_phi_q[BH*NSEQ*MM];     // 8 MB
__device__ float g_phi_k[BH*NSEQ*MM];     // 8 MB
__device__ float g_skv[BH*CC*MM*DD];      // 8 MB  (chunk KV sums -> exclusive prefix)
__device__ float g_sk [BH*CC*MM];         // 256 KB

// ---------------------------------------------------------------------------
// Kernel 1: per block = 4 chunks (128 tokens), 256 threads, 72KB dynamic smem.
// grid 256 -> 2 CTA/SM suffices for one wave -> 128-reg budget.
// phi: thread = (token quad, m-group of 8): 32 u64 accumulators,
// 32 FFMA2 per omega LDS pair -> deep FMA runs, room for load prefetch.
// ---------------------------------------------------------------------------
__global__ void __launch_bounds__(256, 2) phi_sum_kernel(
    const float* __restrict__ q, const float* __restrict__ k,
    const float* __restrict__ v, const float* __restrict__ omega)
{
    extern __shared__ float smem[];
    float* om_t = smem;            // [d][m]           2048 floats (8 KB)
    float* xq   = smem + 2048;     // 128 tok x 32 d   4096 floats (16 KB); v later
    float* xk   = smem + 6144;     //                  4096 floats (16 KB)
    float* pk_s = smem + 10240;    // [t][m] 128x64    8192 floats (32 KB)

    int tid = threadIdx.x;
    int blk = blockIdx.x;                    // bh*16 + cq
    int bh  = blk >> 4;
    int cq  = blk & 15;                      // chunk quad
    int base_tok = bh*NSEQ + cq*128;

    // omega[m][d] -> om_t[d][m], conflict-free stores
    {
        int m = tid & 63;
        int d0 = (tid >> 6) * 8;
        #pragma unroll
        for (int jj = 0; jj < 8; jj++) {
            int d = d0 + jj;
            om_t[d*MM + m] = omega[m*DD + d];
        }
    }
    // load 128 tokens of q,k (1024 float4 each)
    {
        const float4* q4 = (const float4*)(q + base_tok*DD);
        const float4* k4 = (const float4*)(k + base_tok*DD);
        #pragma unroll
        for (int i = 0; i < 4; i++) {
            ((float4*)xq)[tid + i*256] = q4[tid + i*256];
            ((float4*)xk)[tid + i*256] = k4[tid + i*256];
        }
    }
    __syncthreads();

    // --- phi phase: 4 tokens x {q,k} x 8 m's per thread ---
    {
        int quad = tid >> 3;          // 0..31 -> tokens quad*4 .. +3
        int mg   = tid & 7;
        int tb = quad*4;
        const ulonglong2* omu = (const ulonglong2*)om_t;  // 16 per d-row
        const float4* xq4 = (const float4*)xq;            // 8 f4 per token
        const float4* xk4 = (const float4*)xk;

        u64 Aq[4][4] = {}, Ak[4][4] = {};
        float nq[4] = {0,0,0,0}, nk[4] = {0,0,0,0};

        #pragma unroll
        for (int dc = 0; dc < 8; dc++) {          // 4 d's per iter
            float4 xqv[4], xkv[4];
            #pragma unroll
            for (int j = 0; j < 4; j++) {
                xqv[j] = xq4[(tb+j)*8 + dc];
                xkv[j] = xk4[(tb+j)*8 + dc];
            }
            #pragma unroll
            for (int dd = 0; dd < 4; dd++) {
                int d = dc*4 + dd;
                ulonglong2 o0 = omu[d*16 + mg];       // 8-addr broadcast
                ulonglong2 o1 = omu[d*16 + 8 + mg];
                #pragma unroll
                for (int j = 0; j < 4; j++) {
                    float a = (dd==0)?xqv[j].x:(dd==1)?xqv[j].y:(dd==2)?xqv[j].z:xqv[j].w;
                    float c = (dd==0)?xkv[j].x:(dd==1)?xkv[j].y:(dd==2)?xkv[j].z:xkv[j].w;
                    u64 aa = pk2(a,a), cc = pk2(c,c);
                    fma2(Aq[j][0], aa, o0.x); fma2(Aq[j][1], aa, o0.y);
                    fma2(Aq[j][2], aa, o1.x); fma2(Aq[j][3], aa, o1.y);
                    fma2(Ak[j][0], cc, o0.x); fma2(Ak[j][1], cc, o0.y);
                    fma2(Ak[j][2], cc, o1.x); fma2(Ak[j][3], cc, o1.y);
                    nq[j] += a*a; nk[j] += c*c;
                }
            }
        }

        #pragma unroll
        for (int j = 0; j < 4; j++) {
            int t = tb + j;
            float nqv = nq[j]*0.5f + LN_SQRT_M;
            float nkv = nk[j]*0.5f + LN_SQRT_M;
            float2 e0, e1, e2, e3;
            float4 plo, phv;
            // q
            e0 = up2(Aq[j][0]); e1 = up2(Aq[j][1]);
            e2 = up2(Aq[j][2]); e3 = up2(Aq[j][3]);
            plo.x = __expf(e0.x - nqv); plo.y = __expf(e0.y - nqv);
            plo.z = __expf(e1.x - nqv); plo.w = __expf(e1.y - nqv);
            phv.x = __expf(e2.x - nqv); phv.y = __expf(e2.y - nqv);
            phv.z = __expf(e3.x - nqv); phv.w = __expf(e3.y - nqv);
            *(float4*)&g_phi_q[(base_tok+t)*MM + mg*4]      = plo;
            *(float4*)&g_phi_q[(base_tok+t)*MM + 32 + mg*4] = phv;
            // k
            e0 = up2(Ak[j][0]); e1 = up2(Ak[j][1]);
            e2 = up2(Ak[j][2]); e3 = up2(Ak[j][3]);
            plo.x = __expf(e0.x - nkv); plo.y = __expf(e0.y - nkv);
            plo.z = __expf(e1.x - nkv); plo.w = __expf(e1.y - nkv);
            phv.x = __expf(e2.x - nkv); phv.y = __expf(e2.y - nkv);
            phv.z = __expf(e3.x - nkv); phv.w = __expf(e3.y - nkv);
            *(float4*)&g_phi_k[(base_tok+t)*MM + mg*4]      = plo;
            *(float4*)&g_phi_k[(base_tok+t)*MM + 32 + mg*4] = phv;
            *(float4*)&pk_s[t*MM + mg*4]      = plo;
            *(float4*)&pk_s[t*MM + 32 + mg*4] = phv;
        }
    }
    __syncthreads();

    // load v (128 tokens) into xq buffer (q dead)
    {
        const float4* v4 = (const float4*)(v + base_tok*DD);
        #pragma unroll
        for (int i = 0; i < 4; i++)
            ((float4*)xq)[tid + i*256] = v4[tid + i*256];
    }
    __syncthreads();

    // --- chunk sums: 64 threads per chunk; thread = m, all 32 d's ---
    {
        int ch = tid >> 6;           // chunk 0..3
        int m  = tid & 63;
        const ulonglong2* vsu = (const ulonglong2*)xq;
        const float* pk = &pk_s[ch*32*MM];
        u64 A[16] = {};
        float ks = 0.f;
        #pragma unroll 4
        for (int t = 0; t < LL; t++) {
            float p = pk[t*MM + m];
            u64 pp = pk2(p, p);
            const ulonglong2* vrow = &vsu[(ch*32+t)*8];
            #pragma unroll
            for (int i = 0; i < 8; i++) {
                ulonglong2 w = vrow[i];
                fma2(A[2*i],   pp, w.x);
                fma2(A[2*i+1], pp, w.y);
            }
            ks += p;
        }
        int blkc = bh*CC + cq*4 + ch;
        ulonglong2* skvU = (ulonglong2*)g_skv + (size_t)(blkc*MM + m)*8;
        #pragma unroll
        for (int i = 0; i < 8; i++) {
            ulonglong2 s; s.x = A[2*i]; s.y = A[2*i+1];
            skvU[i] = s;
        }
        g_sk[blkc*MM + m] = ks;
    }
}

// ---------------------------------------------------------------------------
// Kernel 2: exclusive prefix scan over chunks (in place), float4 for skv.
// ---------------------------------------------------------------------------
__global__ void scan_kernel()
{
    int idx = blockIdx.x * blockDim.x + threadIdx.x;
    const int NSKV = BH*MM*8;        // float4 series
    if (idx < NSKV) {
        int bh = idx / (MM*8);
        int r  = idx % (MM*8);       // m*8 + d4
        float4* base = (float4*)g_skv + (size_t)bh*CC*MM*8 + r;
        float4 run = {0,0,0,0};
        #pragma unroll 4
        for (int c = 0; c < CC; c++) {
            float4 t = base[(size_t)c*MM*8];
            base[(size_t)c*MM*8] = run;
            run.x += t.x; run.y += t.y; run.z += t.z; run.w += t.w;
        }
    } else if (idx < NSKV + BH*MM) {
        int j  = idx - NSKV;
        int bh = j / MM, m = j % MM;
        float* base = g_sk + bh*CC*MM + m;
        float run = 0.f;
        #pragma unroll 4
        for (int c = 0; c < CC; c++) {
            float t = base[c*MM];
            base[c*MM] = run;
            run += t;
        }
    }
}

// ---------------------------------------------------------------------------
// Kernel 3: per-(bh,chunk) output (R12 known-good: no atomics, triangular B).
// ---------------------------------------------------------------------------
__global__ void __launch_bounds__(256) out_kernel(
    const float* __restrict__ v, float* __restrict__ out)
{
    __shared__ float pq_p[LL*68];    // [i][m], row stride 17 f4, 8.5 KB
    __shared__ float buf [MM*DD];    // pk [j][m] in A, then Sp [m][d] in B
    __shared__ float vs  [LL*DD];
    __shared__ float A_p [LL*33];    // [i][j], row stride 33 (masked entries = 0)
    __shared__ float kp  [MM];
    __shared__ float s_qk[LL];       // phi_q[i] . kp

    int tid = threadIdx.x;
    int blk = blockIdx.x;
    int base_tok = (blk/CC)*NSEQ + (blk%CC)*LL;

    // Early Sp loads -> registers (consumed after Phase A)
    const float4* gs4 = (const float4*)&g_skv[(size_t)blk*MM*DD];
    float4 sp_r0 = gs4[tid];
    float4 sp_r1 = gs4[tid + 256];

    {
        const float4* gq4 = (const float4*)&g_phi_q[base_tok*MM];
        const float4* gk4 = (const float4*)&g_phi_k[base_tok*MM];
        const float4* gv4 = (const float4*)(v + base_tok*DD);
        float4* pq4w = (float4*)pq_p;
        #pragma unroll
        for (int r = 0; r < 2; r++) {
            int idx = tid + r*256;               // i*16 + m4
            int i = idx >> 4, m4 = idx & 15;
            pq4w[i*17 + m4] = gq4[idx];
            ((float4*)buf)[idx] = gk4[idx];      // pk [j][m]
        }
        ((float4*)vs)[tid] = gv4[tid];
        if (tid < MM) kp[tid] = g_sk[blk*MM + tid];
    }
    __syncthreads();

    // --- Phase A: i = lane, warp w owns j = w*4 .. w*4+3; packed dots ---
    {
        int i = tid & 31;
        int w = tid >> 5;
        int j0 = w * 4;
        const ulonglong2* pqU = (const ulonglong2*)pq_p;
        const ulonglong2* pkU = (const ulonglong2*)buf;
        const ulonglong2* kpU = (const ulonglong2*)kp;
        u64 D0=0, D1=0, D2=0, D3=0, QK=0;
        #pragma unroll
        for (int m4 = 0; m4 < 16; m4++) {
            ulonglong2 qv = pqU[i*17 + m4];
            ulonglong2 k0 = pkU[(j0+0)*16 + m4];
            ulonglong2 k1 = pkU[(j0+1)*16 + m4];
            ulonglong2 k2 = pkU[(j0+2)*16 + m4];
            ulonglong2 k3 = pkU[(j0+3)*16 + m4];
            fma2(D0, qv.x, k0.x); fma2(D0, qv.y, k0.y);
            fma2(D1, qv.x, k1.x); fma2(D1, qv.y, k1.y);
            fma2(D2, qv.x, k2.x); fma2(D2, qv.y, k2.y);
            fma2(D3, qv.x, k3.x); fma2(D3, qv.y, k3.y);
            if (w == 0) {
                ulonglong2 kv = kpU[m4];
                fma2(QK, qv.x, kv.x); fma2(QK, qv.y, kv.y);
            }
        }
        float2 f0 = up2(D0), f1 = up2(D1), f2 = up2(D2), f3 = up2(D3);
        float a0 = f0.x + f0.y, a1 = f1.x + f1.y;
        float a2 = f2.x + f2.y, a3 = f3.x + f3.y;
        if (j0+0 > i) a0 = 0.f;
        if (j0+1 > i) a1 = 0.f;
        if (j0+2 > i) a2 = 0.f;
        if (j0+3 > i) a3 = 0.f;
        A_p[i*33 + j0+0] = a0;
        A_p[i*33 + j0+1] = a1;
        A_p[i*33 + j0+2] = a2;
        A_p[i*33 + j0+3] = a3;
        if (w == 0) {
            float2 fq = up2(QK);
            s_qk[i] = fq.x + fq.y + 1e-6f;
        }
    }
    __syncthreads();

    // pk dead: store prefetched Sp registers into buf
    ((float4*)buf)[tid]       = sp_r0;
    ((float4*)buf)[tid + 256] = sp_r1;
    __syncthreads();

    // --- Phase B (packed, triangular j-loop, inline den) ---
    {
        int i = tid >> 3;
        int g = tid & 7;
        const float4* pq4 = (const float4*)pq_p;
        const ulonglong2* SpU = (const ulonglong2*)buf;
        const ulonglong2* vsU = (const ulonglong2*)vs;
        u64 O0 = 0, O1 = 0;     // {o.x,o.y}, {o.z,o.w}
        #pragma unroll
        for (int m4 = 0; m4 < 16; m4++) {
            float4 qv = pq4[i*17 + m4];
            ulonglong2 s0 = SpU[(m4*4+0)*8 + g];
            ulonglong2 s1 = SpU[(m4*4+1)*8 + g];
            ulonglong2 s2 = SpU[(m4*4+2)*8 + g];
            ulonglong2 s3 = SpU[(m4*4+3)*8 + g];
            u64 t;
            t = pk2(qv.x, qv.x); fma2(O0, t, s0.x); fma2(O1, t, s0.y);
            t = pk2(qv.y, qv.y); fma2(O0, t, s1.x); fma2(O1, t, s1.y);
            t = pk2(qv.z, qv.z); fma2(O0, t, s2.x); fma2(O1, t, s2.y);
            t = pk2(qv.w, qv.w); fma2(O0, t, s3.x); fma2(O1, t, s3.y);
        }
        // Triangular A@v: bound (i|3) is identical across the warp
        int jmax = i | 3;              // >= i; A entries beyond i are stored 0
        float den = s_qk[i];           // includes +1e-6
        for (int j = 0; j <= jmax; j++) {
            float a = A_p[i*33 + j];
            den += a;                  // masked entries contribute 0
            u64 aa = pk2(a, a);
            ulonglong2 vv = vsU[j*8 + g];
            fma2(O0, aa, vv.x); fma2(O1, aa, vv.y);
        }
        float dinv = 1.0f / den;
        float2 o01 = up2(O0), o23 = up2(O1);
        float4* o4 = (float4*)&out[(base_tok + i)*DD + g*4];
        *o4 = make_float4(o01.x*dinv, o01.y*dinv, o23.x*dinv, o23.y*dinv);
    }
}

// ---------------------------------------------------------------------------
extern "C" void kernel_launch(void* const* d_in, const int* in_sizes, int n_in,
                              void* d_out, int out_size)
{
    const float* q     = (const float*)d_in[0];
    const float* k     = (const float*)d_in[1];
    const float* v     = (const float*)d_in[2];
    const float* omega = (const float*)d_in[3];
    float* out = (float*)d_out;

    const int PHI_SMEM = 18432 * 4;   // 72 KB dynamic
    cudaFuncSetAttribute(phi_sum_kernel,
                         cudaFuncAttributeMaxDynamicSharedMemorySize, PHI_SMEM);

    phi_sum_kernel<<<BH*16, 256, PHI_SMEM>>>(q, k, v, omega);
    const int scan_threads = BH*MM*8 + BH*MM;
    scan_kernel<<<(scan_threads + 255)/256, 256>>>();
    out_kernel<<<BH*CC, 256>>>(v, out);
}

// round 14
// speedup vs baseline: 1.1709x; 1.0503x over previous
#include <cuda_runtime.h>

#define BH 16
#define NSEQ 2048
#define DD 32
#define MM 64
#define LL 32
#define CC (NSEQ/LL)   // 64 chunks

typedef unsigned long long u64;

// packed f32x2 helpers (Blackwell FFMA2: ptxas never auto-fuses; PTX-only)
__device__ __forceinline__ u64 pk2(float x, float y) {
    u64 r; asm("mov.b64 %0, {%1, %2};" : "=l"(r) : "f"(x), "f"(y)); return r;
}
__device__ __forceinline__ void fma2(u64& d, u64 a, u64 b) {
    asm("fma.rn.f32x2 %0, %1, %2, %0;" : "+l"(d) : "l"(a), "l"(b));
}
__device__ __forceinline__ float2 up2(u64 a) {
    float2 f; asm("mov.b64 {%0, %1}, %2;" : "=f"(f.x), "=f"(f.y) : "l"(a)); return f;
}

// tf32 helpers
__device__ __forceinline__ unsigned cvt_tf32(float x) {
    unsigned r; asm("cvt.rna.tf32.f32 %0, %1;" : "=r"(r) : "f"(x)); return r;
}
__device__ __forceinline__ void mma_tf32(float* c, const unsigned* a, const unsigned* b) {
    asm("mma.sync.aligned.m16n8k8.row.col.f32.tf32.tf32.f32 "
        "{%0,%1,%2,%3}, {%4,%5,%6,%7}, {%8,%9}, {%0,%1,%2,%3};"
        : "+f"(c[0]), "+f"(c[1]), "+f"(c[2]), "+f"(c[3])
        : "r"(a[0]), "r"(a[1]), "r"(a[2]), "r"(a[3]), "r"(b[0]), "r"(b[1]));
}

#define LN_SQRT_M 2.0794415416798357f   // ln(8): folds the 1/sqrt(64) factor

// Scratch (device globals: no allocation allowed in kernel_launch)
__device__ float g_phi_q[BH*NSEQ*MM];     // 8 MB
__device__ float g_phi_k[BH*NSEQ*MM];     // 8 MB
__device__ float g_skv[BH*CC*MM*DD];      // 8 MB  (chunk KV sums -> exclusive prefix)
__device__ float g_sk [BH*CC*MM];         // 256 KB

// smem float offsets (overlaid regions; see phase comments)
#define OFF_OM   0          // 32 x 72 tf32 bits          (mma phase)
#define OFF_XQ   2304       // 128 tok x 36 padded fp32   (mma phase)
#define OFF_XK   6912       // 128 tok x 36               (mma phase)
#define OFF_PKS  0          // 128 x 72 phi_k             (epilogue+sums; overlays OM/XQ)
#define OFF_VS   9216       // 128 x 32 v                 (sums; overlays XK tail)
#define OFF_NQ   13312      // 128 norms q
#define OFF_NK   13440      // 128 norms k
#define PHI_SMEM_FLOATS 13568
#define PHI_SMEM_BYTES  (PHI_SMEM_FLOATS*4)   // 54272

// ---------------------------------------------------------------------------
// Kernel 1: per block = 4 chunks (128 tokens), 256 threads (8 warps).
// proj via tf32 mma.m16n8k8 (warp = 16-token tile); norms in full fp32
// (a tf32 norm would be a correlated per-token error that doesn't cancel).
// ---------------------------------------------------------------------------
__global__ void __launch_bounds__(256, 2) phi_sum_kernel(
    const float* __restrict__ q, const float* __restrict__ k,
    const float* __restrict__ v, const float* __restrict__ omega)
{
    extern __shared__ float smem[];
    float* om_t = smem + OFF_OM;     // [d][m] stride 72, tf32 bits
    float* xq   = smem + OFF_XQ;     // [t][d] stride 36, fp32
    float* xk   = smem + OFF_XK;
    float* pk_s = smem + OFF_PKS;    // [t][m] stride 72 (epilogue on)
    float* vs   = smem + OFF_VS;     // [t][d] stride 32
    float* nq_s = smem + OFF_NQ;
    float* nk_s = smem + OFF_NK;

    int tid = threadIdx.x;
    int blk = blockIdx.x;                    // bh*16 + cq
    int bh  = blk >> 4;
    int cq  = blk & 15;
    int base_tok = bh*NSEQ + cq*128;

    // omega[m][d] -> om_t[d][m] (stride 72), converted to tf32 bits
    {
        int m = tid & 63;
        int d0 = (tid >> 6) * 8;
        #pragma unroll
        for (int jj = 0; jj < 8; jj++) {
            int d = d0 + jj;
            ((unsigned*)om_t)[d*72 + m] = cvt_tf32(omega[m*DD + d]);
        }
    }
    // load 128 tokens of q,k into padded stride-36 rows
    {
        const float4* q4 = (const float4*)(q + base_tok*DD);
        const float4* k4 = (const float4*)(k + base_tok*DD);
        #pragma unroll
        for (int r = 0; r < 4; r++) {
            int idx = tid + r*256;           // t*8 + j
            int t = idx >> 3, j = idx & 7;
            *(float4*)(xq + t*36 + j*4) = q4[idx];
            *(float4*)(xk + t*36 + j*4) = k4[idx];
        }
    }
    __syncthreads();

    // full-fp32 norms (threads 0-127: q; 128-255: k)
    {
        int t = tid & 127;
        const float* src = (tid < 128) ? (xq + t*36) : (xk + t*36);
        float n = 0.f;
        #pragma unroll
        for (int j = 0; j < 8; j++) {
            float4 xv = *(const float4*)(src + j*4);
            n += xv.x*xv.x + xv.y*xv.y + xv.z*xv.z + xv.w*xv.w;
        }
        n = n*0.5f + LN_SQRT_M;
        if (tid < 128) nq_s[t] = n; else nk_s[t] = n;
    }
    // (post-mma __syncthreads orders norm writes before epilogue reads)

    // --- MMA phase: warp w owns tokens w*16..w*16+15 ---
    int w = tid >> 5, lane = tid & 31;
    int g = lane >> 2, i = lane & 3;
    int t0 = w * 16;
    float cq_[8][4] = {}, ck_[8][4] = {};
    {
        const unsigned* omb = (const unsigned*)om_t;
        #pragma unroll
        for (int ks = 0; ks < 4; ks++) {
            int k0 = ks*8;
            unsigned aq[4], ak[4];
            aq[0] = cvt_tf32(xq[(t0+g  )*36 + k0+i  ]);
            aq[1] = cvt_tf32(xq[(t0+g+8)*36 + k0+i  ]);
            aq[2] = cvt_tf32(xq[(t0+g  )*36 + k0+i+4]);
            aq[3] = cvt_tf32(xq[(t0+g+8)*36 + k0+i+4]);
            ak[0] = cvt_tf32(xk[(t0+g  )*36 + k0+i  ]);
            ak[1] = cvt_tf32(xk[(t0+g+8)*36 + k0+i  ]);
            ak[2] = cvt_tf32(xk[(t0+g  )*36 + k0+i+4]);
            ak[3] = cvt_tf32(xk[(t0+g+8)*36 + k0+i+4]);
            #pragma unroll
            for (int n = 0; n < 8; n++) {
                unsigned b[2];
                b[0] = omb[(k0+i  )*72 + n*8 + g];
                b[1] = omb[(k0+4+i)*72 + n*8 + g];
                mma_tf32(cq_[n], aq, b);
                mma_tf32(ck_[n], ak, b);
            }
        }
    }
    __syncthreads();   // all xq/xk/om reads done; norms visible

    // --- epilogue: exp + store (pk_s overlay + globals); also load v ---
    {
        int r0 = t0 + g, r1 = t0 + g + 8;
        float n_q0 = nq_s[r0], n_q1 = nq_s[r1];
        float n_k0 = nk_s[r0], n_k1 = nk_s[r1];
        #pragma unroll
        for (int n = 0; n < 8; n++) {
            int col = n*8 + 2*i;
            float2 pq0, pq1, pk0, pk1;
            pq0.x = __expf(cq_[n][0] - n_q0); pq0.y = __expf(cq_[n][1] - n_q0);
            pq1.x = __expf(cq_[n][2] - n_q1); pq1.y = __expf(cq_[n][3] - n_q1);
            pk0.x = __expf(ck_[n][0] - n_k0); pk0.y = __expf(ck_[n][1] - n_k0);
            pk1.x = __expf(ck_[n][2] - n_k1); pk1.y = __expf(ck_[n][3] - n_k1);
            *(float2*)&g_phi_q[(base_tok + r0)*MM + col] = pq0;
            *(float2*)&g_phi_q[(base_tok + r1)*MM + col] = pq1;
            *(float2*)&g_phi_k[(base_tok + r0)*MM + col] = pk0;
            *(float2*)&g_phi_k[(base_tok + r1)*MM + col] = pk1;
            *(float2*)&pk_s[r0*72 + col] = pk0;
            *(float2*)&pk_s[r1*72 + col] = pk1;
        }
        // v load (overlays dead xk region)
        const float4* v4 = (const float4*)(v + base_tok*DD);
        #pragma unroll
        for (int r = 0; r < 4; r++)
            ((float4*)vs)[tid + r*256] = v4[tid + r*256];
    }
    __syncthreads();

    // --- chunk sums: 64 threads per chunk; thread = m, all 32 d's ---
    {
        int ch = tid >> 6;           // chunk 0..3
        int m  = tid & 63;
        const ulonglong2* vsu = (const ulonglong2*)vs;
        const float* pk = pk_s + ch*32*72;
        u64 A[16] = {};
        float ks = 0.f;
        #pragma unroll 4
        for (int t = 0; t < LL; t++) {
            float p = pk[t*72 + m];
            u64 pp = pk2(p, p);
            const ulonglong2* vrow = &vsu[(ch*32+t)*8];
            #pragma unroll
            for (int j = 0; j < 8; j++) {
                ulonglong2 wv = vrow[j];
                fma2(A[2*j],   pp, wv.x);
                fma2(A[2*j+1], pp, wv.y);
            }
            ks += p;
        }
        int blkc = bh*CC + cq*4 + ch;
        ulonglong2* skvU = (ulonglong2*)g_skv + (size_t)(blkc*MM + m)*8;
        #pragma unroll
        for (int j = 0; j < 8; j++) {
            ulonglong2 s; s.x = A[2*j]; s.y = A[2*j+1];
            skvU[j] = s;
        }
        g_sk[blkc*MM + m] = ks;
    }
}

// ---------------------------------------------------------------------------
// Kernel 2: exclusive prefix scan over chunks (in place), float4 for skv.
// ---------------------------------------------------------------------------
__global__ void scan_kernel()
{
    int idx = blockIdx.x * blockDim.x + threadIdx.x;
    const int NSKV = BH*MM*8;        // float4 series
    if (idx < NSKV) {
        int bh = idx / (MM*8);
        int r  = idx % (MM*8);       // m*8 + d4
        float4* base = (float4*)g_skv + (size_t)bh*CC*MM*8 + r;
        float4 run = {0,0,0,0};
        #pragma unroll 4
        for (int c = 0; c < CC; c++) {
            float4 t = base[(size_t)c*MM*8];
            base[(size_t)c*MM*8] = run;
            run.x += t.x; run.y += t.y; run.z += t.z; run.w += t.w;
        }
    } else if (idx < NSKV + BH*MM) {
        int j  = idx - NSKV;
        int bh = j / MM, m = j % MM;
        float* base = g_sk + bh*CC*MM + m;
        float run = 0.f;
        #pragma unroll 4
        for (int c = 0; c < CC; c++) {
            float t = base[c*MM];
            base[c*MM] = run;
            run += t;
        }
    }
}

// ---------------------------------------------------------------------------
// Kernel 3: per-(bh,chunk) output (R12/13 known-good).
// ---------------------------------------------------------------------------
__global__ void __launch_bounds__(256) out_kernel(
    const float* __restrict__ v, float* __restrict__ out)
{
    __shared__ float pq_p[LL*68];    // [i][m], row stride 17 f4, 8.5 KB
    __shared__ float buf [MM*DD];    // pk [j][m] in A, then Sp [m][d] in B
    __shared__ float vs  [LL*DD];
    __shared__ float A_p [LL*33];    // [i][j], row stride 33 (masked entries = 0)
    __shared__ float kp  [MM];
    __shared__ float s_qk[LL];       // phi_q[i] . kp

    int tid = threadIdx.x;
    int blk = blockIdx.x;
    int base_tok = (blk/CC)*NSEQ + (blk%CC)*LL;

    // Early Sp loads -> registers (consumed after Phase A)
    const float4* gs4 = (const float4*)&g_skv[(size_t)blk*MM*DD];
    float4 sp_r0 = gs4[tid];
    float4 sp_r1 = gs4[tid + 256];

    {
        const float4* gq4 = (const float4*)&g_phi_q[base_tok*MM];
        const float4* gk4 = (const float4*)&g_phi_k[base_tok*MM];
        const float4* gv4 = (const float4*)(v + base_tok*DD);
        float4* pq4w = (float4*)pq_p;
        #pragma unroll
        for (int r = 0; r < 2; r++) {
            int idx = tid + r*256;               // i*16 + m4
            int i = idx >> 4, m4 = idx & 15;
            pq4w[i*17 + m4] = gq4[idx];
            ((float4*)buf)[idx] = gk4[idx];      // pk [j][m]
        }
        ((float4*)vs)[tid] = gv4[tid];
        if (tid < MM) kp[tid] = g_sk[blk*MM + tid];
    }
    __syncthreads();

    // --- Phase A: i = lane, warp w owns j = w*4 .. w*4+3; packed dots ---
    {
        int i = tid & 31;
        int w = tid >> 5;
        int j0 = w * 4;
        const ulonglong2* pqU = (const ulonglong2*)pq_p;
        const ulonglong2* pkU = (const ulonglong2*)buf;
        const ulonglong2* kpU = (const ulonglong2*)kp;
        u64 D0=0, D1=0, D2=0, D3=0, QK=0;
        #pragma unroll
        for (int m4 = 0; m4 < 16; m4++) {
            ulonglong2 qv = pqU[i*17 + m4];
            ulonglong2 k0 = pkU[(j0+0)*16 + m4];
            ulonglong2 k1 = pkU[(j0+1)*16 + m4];
            ulonglong2 k2 = pkU[(j0+2)*16 + m4];
            ulonglong2 k3 = pkU[(j0+3)*16 + m4];
            fma2(D0, qv.x, k0.x); fma2(D0, qv.y, k0.y);
            fma2(D1, qv.x, k1.x); fma2(D1, qv.y, k1.y);
            fma2(D2, qv.x, k2.x); fma2(D2, qv.y, k2.y);
            fma2(D3, qv.x, k3.x); fma2(D3, qv.y, k3.y);
            if (w == 0) {
                ulonglong2 kv = kpU[m4];
                fma2(QK, qv.x, kv.x); fma2(QK, qv.y, kv.y);
            }
        }
        float2 f0 = up2(D0), f1 = up2(D1), f2 = up2(D2), f3 = up2(D3);
        float a0 = f0.x + f0.y, a1 = f1.x + f1.y;
        float a2 = f2.x + f2.y, a3 = f3.x + f3.y;
        if (j0+0 > i) a0 = 0.f;
        if (j0+1 > i) a1 = 0.f;
        if (j0+2 > i) a2 = 0.f;
        if (j0+3 > i) a3 = 0.f;
        A_p[i*33 + j0+0] = a0;
        A_p[i*33 + j0+1] = a1;
        A_p[i*33 + j0+2] = a2;
        A_p[i*33 + j0+3] = a3;
        if (w == 0) {
            float2 fq = up2(QK);
            s_qk[i] = fq.x + fq.y + 1e-6f;
        }
    }
    __syncthreads();

    // pk dead: store prefetched Sp registers into buf
    ((float4*)buf)[tid]       = sp_r0;
    ((float4*)buf)[tid + 256] = sp_r1;
    __syncthreads();

    // --- Phase B (packed, triangular j-loop, inline den) ---
    {
        int i = tid >> 3;
        int g = tid & 7;
        const float4* pq4 = (const float4*)pq_p;
        const ulonglong2* SpU = (const ulonglong2*)buf;
        const ulonglong2* vsU = (const ulonglong2*)vs;
        u64 O0 = 0, O1 = 0;     // {o.x,o.y}, {o.z,o.w}
        #pragma unroll
        for (int m4 = 0; m4 < 16; m4++) {
            float4 qv = pq4[i*17 + m4];
            ulonglong2 s0 = SpU[(m4*4+0)*8 + g];
            ulonglong2 s1 = SpU[(m4*4+1)*8 + g];
            ulonglong2 s2 = SpU[(m4*4+2)*8 + g];
            ulonglong2 s3 = SpU[(m4*4+3)*8 + g];
            u64 t;
            t = pk2(qv.x, qv.x); fma2(O0, t, s0.x); fma2(O1, t, s0.y);
            t = pk2(qv.y, qv.y); fma2(O0, t, s1.x); fma2(O1, t, s1.y);
            t = pk2(qv.z, qv.z); fma2(O0, t, s2.x); fma2(O1, t, s2.y);
            t = pk2(qv.w, qv.w); fma2(O0, t, s3.x); fma2(O1, t, s3.y);
        }
        // Triangular A@v: bound (i|3) is identical across the warp
        int jmax = i | 3;              // >= i; A entries beyond i are stored 0
        float den = s_qk[i];           // includes +1e-6
        for (int j = 0; j <= jmax; j++) {
            float a = A_p[i*33 + j];
            den += a;                  // masked entries contribute 0
            u64 aa = pk2(a, a);
            ulonglong2 vv = vsU[j*8 + g];
            fma2(O0, aa, vv.x); fma2(O1, aa, vv.y);
        }
        float dinv = 1.0f / den;
        float2 o01 = up2(O0), o23 = up2(O1);
        float4* o4 = (float4*)&out[(base_tok + i)*DD + g*4];
        *o4 = make_float4(o01.x*dinv, o01.y*dinv, o23.x*dinv, o23.y*dinv);
    }
}

// ---------------------------------------------------------------------------
extern "C" void kernel_launch(void* const* d_in, const int* in_sizes, int n_in,
                              void* d_out, int out_size)
{
    const float* q     = (const float*)d_in[0];
    const float* k     = (const float*)d_in[1];
    const float* v     = (const float*)d_in[2];
    const float* omega = (const float*)d_in[3];
    float* out = (float*)d_out;

    cudaFuncSetAttribute(phi_sum_kernel,
                         cudaFuncAttributeMaxDynamicSharedMemorySize, PHI_SMEM_BYTES);

    phi_sum_kernel<<<BH*16, 256, PHI_SMEM_BYTES>>>(q, k, v, omega);
    const int scan_threads = BH*MM*8 + BH*MM;
    scan_kernel<<<(scan_threads + 255)/256, 256>>>();
    out_kernel<<<BH*CC, 256>>>(v, out);
}

// round 15
// speedup vs baseline: 1.5055x; 1.2858x over previous
#include <cuda_runtime.h>

#define BH 16
#define NSEQ 2048
#define DD 32
#define MM 64
#define LL 32
#define CC (NSEQ/LL)   // 64 chunks

typedef unsigned long long u64;

// packed f32x2 helpers
__device__ __forceinline__ u64 pk2(float x, float y) {
    u64 r; asm("mov.b64 %0, {%1, %2};" : "=l"(r) : "f"(x), "f"(y)); return r;
}
__device__ __forceinline__ void fma2(u64& d, u64 a, u64 b) {
    asm("fma.rn.f32x2 %0, %1, %2, %0;" : "+l"(d) : "l"(a), "l"(b));
}
__device__ __forceinline__ float2 up2(u64 a) {
    float2 f; asm("mov.b64 {%0, %1}, %2;" : "=f"(f.x), "=f"(f.y) : "l"(a)); return f;
}

// tf32 helpers
__device__ __forceinline__ unsigned cvt_tf32(float x) {
    unsigned r; asm("cvt.rna.tf32.f32 %0, %1;" : "=r"(r) : "f"(x)); return r;
}
__device__ __forceinline__ void mma_tf32(float* c, const unsigned* a, const unsigned* b) {
    asm("mma.sync.aligned.m16n8k8.row.col.f32.tf32.tf32.f32 "
        "{%0,%1,%2,%3}, {%4,%5,%6,%7}, {%8,%9}, {%0,%1,%2,%3};"
        : "+f"(c[0]), "+f"(c[1]), "+f"(c[2]), "+f"(c[3])
        : "r"(a[0]), "r"(a[1]), "r"(a[2]), "r"(a[3]), "r"(b[0]), "r"(b[1]));
}

#define LN_SQRT_M 2.0794415416798357f   // ln(8): folds the 1/sqrt(64) factor

// Scratch (device globals)
__device__ float g_phi_q[BH*NSEQ*MM];     // 8 MB
__device__ float g_phi_k[BH*NSEQ*MM];     // 8 MB
__device__ float g_skv[BH*CC*MM*DD];      // 8 MB
__device__ float g_sk [BH*CC*MM];         // 256 KB

// phi kernel smem offsets (R14 known-good)
#define OFF_OM   0
#define OFF_XQ   2304
#define OFF_XK   6912
#define OFF_PKS  0
#define OFF_VS   9216
#define OFF_NQ   13312
#define OFF_NK   13440
#define PHI_SMEM_FLOATS 13568
#define PHI_SMEM_BYTES  (PHI_SMEM_FLOATS*4)

// ---------------------------------------------------------------------------
// Kernel 1 (R14 known-good): tf32 MMA projections, fp32 norms, scalar chunk sums.
// ---------------------------------------------------------------------------
__global__ void __launch_bounds__(256, 2) phi_sum_kernel(
    const float* __restrict__ q, const float* __restrict__ k,
    const float* __restrict__ v, const float* __restrict__ omega)
{
    extern __shared__ float smem[];
    float* om_t = smem + OFF_OM;
    float* xq   = smem + OFF_XQ;
    float* xk   = smem + OFF_XK;
    float* pk_s = smem + OFF_PKS;
    float* vs   = smem + OFF_VS;
    float* nq_s = smem + OFF_NQ;
    float* nk_s = smem + OFF_NK;

    int tid = threadIdx.x;
    int blk = blockIdx.x;
    int bh  = blk >> 4;
    int cq  = blk & 15;
    int base_tok = bh*NSEQ + cq*128;

    {
        int m = tid & 63;
        int d0 = (tid >> 6) * 8;
        #pragma unroll
        for (int jj = 0; jj < 8; jj++) {
            int d = d0 + jj;
            ((unsigned*)om_t)[d*72 + m] = cvt_tf32(omega[m*DD + d]);
        }
    }
    {
        const float4* q4 = (const float4*)(q + base_tok*DD);
        const float4* k4 = (const float4*)(k + base_tok*DD);
        #pragma unroll
        for (int r = 0; r < 4; r++) {
            int idx = tid + r*256;
            int t = idx >> 3, j = idx & 7;
            *(float4*)(xq + t*36 + j*4) = q4[idx];
            *(float4*)(xk + t*36 + j*4) = k4[idx];
        }
    }
    __syncthreads();

    {
        int t = tid & 127;
        const float* src = (tid < 128) ? (xq + t*36) : (xk + t*36);
        float n = 0.f;
        #pragma unroll
        for (int j = 0; j < 8; j++) {
            float4 xv = *(const float4*)(src + j*4);
            n += xv.x*xv.x + xv.y*xv.y + xv.z*xv.z + xv.w*xv.w;
        }
        n = n*0.5f + LN_SQRT_M;
        if (tid < 128) nq_s[t] = n; else nk_s[t] = n;
    }

    int w = tid >> 5, lane = tid & 31;
    int g = lane >> 2, i = lane & 3;
    int t0 = w * 16;
    float cq_[8][4] = {}, ck_[8][4] = {};
    {
        const unsigned* omb = (const unsigned*)om_t;
        #pragma unroll
        for (int ks = 0; ks < 4; ks++) {
            int k0 = ks*8;
            unsigned aq[4], ak[4];
            aq[0] = cvt_tf32(xq[(t0+g  )*36 + k0+i  ]);
            aq[1] = cvt_tf32(xq[(t0+g+8)*36 + k0+i  ]);
            aq[2] = cvt_tf32(xq[(t0+g  )*36 + k0+i+4]);
            aq[3] = cvt_tf32(xq[(t0+g+8)*36 + k0+i+4]);
            ak[0] = cvt_tf32(xk[(t0+g  )*36 + k0+i  ]);
            ak[1] = cvt_tf32(xk[(t0+g+8)*36 + k0+i  ]);
            ak[2] = cvt_tf32(xk[(t0+g  )*36 + k0+i+4]);
            ak[3] = cvt_tf32(xk[(t0+g+8)*36 + k0+i+4]);
            #pragma unroll
            for (int n = 0; n < 8; n++) {
                unsigned b[2];
                b[0] = omb[(k0+i  )*72 + n*8 + g];
                b[1] = omb[(k0+4+i)*72 + n*8 + g];
                mma_tf32(cq_[n], aq, b);
                mma_tf32(ck_[n], ak, b);
            }
        }
    }
    __syncthreads();

    {
        int r0 = t0 + g, r1 = t0 + g + 8;
        float n_q0 = nq_s[r0], n_q1 = nq_s[r1];
        float n_k0 = nk_s[r0], n_k1 = nk_s[r1];
        #pragma unroll
        for (int n = 0; n < 8; n++) {
            int col = n*8 + 2*i;
            float2 pq0, pq1, pk0, pk1;
            pq0.x = __expf(cq_[n][0] - n_q0); pq0.y = __expf(cq_[n][1] - n_q0);
            pq1.x = __expf(cq_[n][2] - n_q1); pq1.y = __expf(cq_[n][3] - n_q1);
            pk0.x = __expf(ck_[n][0] - n_k0); pk0.y = __expf(ck_[n][1] - n_k0);
            pk1.x = __expf(ck_[n][2] - n_k1); pk1.y = __expf(ck_[n][3] - n_k1);
            *(float2*)&g_phi_q[(base_tok + r0)*MM + col] = pq0;
            *(float2*)&g_phi_q[(base_tok + r1)*MM + col] = pq1;
            *(float2*)&g_phi_k[(base_tok + r0)*MM + col] = pk0;
            *(float2*)&g_phi_k[(base_tok + r1)*MM + col] = pk1;
            *(float2*)&pk_s[r0*72 + col] = pk0;
            *(float2*)&pk_s[r1*72 + col] = pk1;
        }
        const float4* v4 = (const float4*)(v + base_tok*DD);
        #pragma unroll
        for (int r = 0; r < 4; r++)
            ((float4*)vs)[tid + r*256] = v4[tid + r*256];
    }
    __syncthreads();

    {
        int ch = tid >> 6;
        int m  = tid & 63;
        const ulonglong2* vsu = (const ulonglong2*)vs;
        const float* pk = pk_s + ch*32*72;
        u64 A[16] = {};
        float ks = 0.f;
        #pragma unroll 4
        for (int t = 0; t < LL; t++) {
            float p = pk[t*72 + m];
            u64 pp = pk2(p, p);
            const ulonglong2* vrow = &vsu[(ch*32+t)*8];
            #pragma unroll
            for (int j = 0; j < 8; j++) {
                ulonglong2 wv = vrow[j];
                fma2(A[2*j],   pp, wv.x);
                fma2(A[2*j+1], pp, wv.y);
            }
            ks += p;
        }
        int blkc = bh*CC + cq*4 + ch;
        ulonglong2* skvU = (ulonglong2*)g_skv + (size_t)(blkc*MM + m)*8;
        #pragma unroll
        for (int j = 0; j < 8; j++) {
            ulonglong2 s; s.x = A[2*j]; s.y = A[2*j+1];
            skvU[j] = s;
        }
        g_sk[blkc*MM + m] = ks;
    }
}

// ---------------------------------------------------------------------------
// Kernel 2: exclusive prefix scan over chunks (in place), float4 for skv.
// ---------------------------------------------------------------------------
__global__ void scan_kernel()
{
    int idx = blockIdx.x * blockDim.x + threadIdx.x;
    const int NSKV = BH*MM*8;
    if (idx < NSKV) {
        int bh = idx / (MM*8);
        int r  = idx % (MM*8);
        float4* base = (float4*)g_skv + (size_t)bh*CC*MM*8 + r;
        float4 run = {0,0,0,0};
        #pragma unroll 4
        for (int c = 0; c < CC; c++) {
            float4 t = base[(size_t)c*MM*8];
            base[(size_t)c*MM*8] = run;
            run.x += t.x; run.y += t.y; run.z += t.z; run.w += t.w;
        }
    } else if (idx < NSKV + BH*MM) {
        int j  = idx - NSKV;
        int bh = j / MM, m = j % MM;
        float* base = g_sk + bh*CC*MM + m;
        float run = 0.f;
        #pragma unroll 4
        for (int c = 0; c < CC; c++) {
            float t = base[c*MM];
            base[c*MM] = run;
            run += t;
        }
    }
}

// ---------------------------------------------------------------------------
// Kernel 3: per-(bh,chunk) output — ALL tf32 MMA.
//   Phase A: A = phi_q phi_k^T (8 MMAs/warp), masked; den partials via shfl;
//            warp 0 keeps the scalar qk = phi_q.kp path.
//   Phase B: out = phi_q@Sp (8 MMAs) + A@v (4 MMAs); den finalized inline.
//   ONE __syncthreads total.
// Warp w: m-tile = w&1 (rows 16mt..), n-tile = w>>2? no: nt = w>>1 (cols 8nt..).
// ---------------------------------------------------------------------------
__global__ void __launch_bounds__(256) out_kernel(
    const float* __restrict__ v, float* __restrict__ out)
{
    __shared__ float pq_p[LL*68];     // [i][m] stride 68 (4r+c bank-unique)
    __shared__ float pk_p[LL*68];     // [j][m] stride 68
    __shared__ float sp_s[MM*40];     // [m][d] stride 40 (8k+n bank-unique)
    __shared__ float v_s [LL*40];     // [j][d] stride 40
    __shared__ float A_s [LL*36];     // [i][j] stride 36 (4r+c bank-unique)
    __shared__ float kp  [MM];
    __shared__ float s_qk[LL];        // phi_q[i].kp + 1e-6
    __shared__ float den_part[4*LL];  // [nt][i]

    int tid = threadIdx.x;
    int blk = blockIdx.x;
    int base_tok = (blk/CC)*NSEQ + (blk%CC)*LL;

    // loads
    {
        const float4* gq4 = (const float4*)&g_phi_q[base_tok*MM];
        const float4* gk4 = (const float4*)&g_phi_k[base_tok*MM];
        const float4* gs4 = (const float4*)&g_skv[(size_t)blk*MM*DD];
        const float4* gv4 = (const float4*)(v + base_tok*DD);
        #pragma unroll
        for (int r = 0; r < 2; r++) {
            int idx = tid + r*256;               // i*16 + m4
            int i = idx >> 4, m4 = idx & 15;
            ((float4*)pq_p)[i*17 + m4] = gq4[idx];
            ((float4*)pk_p)[i*17 + m4] = gk4[idx];
            int m = idx >> 3, j = idx & 7;       // Sp: m*8 + j
            *(float4*)(sp_s + m*40 + j*4) = gs4[idx];
        }
        int t = tid >> 3, j = tid & 7;
        *(float4*)(v_s + t*40 + j*4) = gv4[tid];
        if (tid < MM) kp[tid] = g_sk[blk*MM + tid];
    }
    __syncthreads();

    int w = tid >> 5, lane = tid & 31;
    int mt = w & 1, nt = w >> 1;
    int r = lane >> 2, cp = lane & 3;
    int row0 = mt*16 + r, row1 = row0 + 8;

    // --- Phase A: A-tile MMAs + mask + den partials (+ warp0 scalar qk) ---
    {
        float cA[4] = {0,0,0,0};
        #pragma unroll
        for (int ks = 0; ks < 8; ks++) {
            int k0 = ks*8;
            unsigned a[4], b[2];
            a[0] = cvt_tf32(pq_p[row0*68 + k0 + cp    ]);
            a[1] = cvt_tf32(pq_p[row1*68 + k0 + cp    ]);
            a[2] = cvt_tf32(pq_p[row0*68 + k0 + cp + 4]);
            a[3] = cvt_tf32(pq_p[row1*68 + k0 + cp + 4]);
            b[0] = cvt_tf32(pk_p[(nt*8 + r)*68 + k0 + cp    ]);
            b[1] = cvt_tf32(pk_p[(nt*8 + r)*68 + k0 + cp + 4]);
            mma_tf32(cA, a, b);
        }
        int col0 = nt*8 + 2*cp, col1 = col0 + 1;
        float m00 = (col0 <= row0) ? cA[0] : 0.f;
        float m01 = (col1 <= row0) ? cA[1] : 0.f;
        float m10 = (col0 <= row1) ? cA[2] : 0.f;
        float m11 = (col1 <= row1) ? cA[3] : 0.f;
        *(float2*)&A_s[row0*36 + col0] = make_float2(m00, m01);
        *(float2*)&A_s[row1*36 + col0] = make_float2(m10, m11);
        float p0 = m00 + m01, p1 = m10 + m11;
        p0 += __shfl_xor_sync(0xffffffffu, p0, 1);
        p0 += __shfl_xor_sync(0xffffffffu, p0, 2);
        p1 += __shfl_xor_sync(0xffffffffu, p1, 1);
        p1 += __shfl_xor_sync(0xffffffffu, p1, 2);
        if (cp == 0) {
            den_part[nt*LL + row0] = p0;
            den_part[nt*LL + row1] = p1;
        }
        // warp 0: scalar qk = phi_q[i].kp (i = lane)
        if (w == 0) {
            const ulonglong2* pqU = (const ulonglong2*)pq_p;
            const ulonglong2* kpU = (const ulonglong2*)kp;
            u64 QK = 0;
            #pragma unroll
            for (int m4 = 0; m4 < 16; m4++) {
                ulonglong2 qv = pqU[lane*17 + m4];
                ulonglong2 kv = kpU[m4];
                fma2(QK, qv.x, kv.x); fma2(QK, qv.y, kv.y);
            }
            float2 fq = up2(QK);
            s_qk[lane] = fq.x + fq.y + 1e-6f;
        }
    }
    __syncthreads();

    // --- Phase B: out-tile = phi_q@Sp (K=64) + A@v (K=32) ---
    {
        float cB[4] = {0,0,0,0};
        #pragma unroll
        for (int ks = 0; ks < 8; ks++) {
            int k0 = ks*8;
            unsigned a[4], b[2];
            a[0] = cvt_tf32(pq_p[row0*68 + k0 + cp    ]);
            a[1] = cvt_tf32(pq_p[row1*68 + k0 + cp    ]);
            a[2] = cvt_tf32(pq_p[row0*68 + k0 + cp + 4]);
            a[3] = cvt_tf32(pq_p[row1*68 + k0 + cp + 4]);
            b[0] = cvt_tf32(sp_s[(k0 + cp    )*40 + nt*8 + r]);
            b[1] = cvt_tf32(sp_s[(k0 + cp + 4)*40 + nt*8 + r]);
            mma_tf32(cB, a, b);
        }
        #pragma unroll
        for (int ks = 0; ks < 4; ks++) {
            int k0 = ks*8;
            unsigned a[4], b[2];
            a[0] = cvt_tf32(A_s[row0*36 + k0 + cp    ]);
            a[1] = cvt_tf32(A_s[row1*36 + k0 + cp    ]);
            a[2] = cvt_tf32(A_s[row0*36 + k0 + cp + 4]);
            a[3] = cvt_tf32(A_s[row1*36 + k0 + cp + 4]);
            b[0] = cvt_tf32(v_s[(k0 + cp    )*40 + nt*8 + r]);
            b[1] = cvt_tf32(v_s[(k0 + cp + 4)*40 + nt*8 + r]);
            mma_tf32(cB, a, b);
        }
        // inline den + divide + store
        float den0 = s_qk[row0] + den_part[row0]        + den_part[LL + row0]
                                + den_part[2*LL + row0] + den_part[3*LL + row0];
        float den1 = s_qk[row1] + den_part[row1]        + den_part[LL + row1]
                                + den_part[2*LL + row1] + den_part[3*LL + row1];
        float i0 = 1.0f / den0, i1 = 1.0f / den1;
        int col0 = nt*8 + 2*cp;
        *(float2*)&out[(base_tok + row0)*DD + col0] = make_float2(cB[0]*i0, cB[1]*i0);
        *(float2*)&out[(base_tok + row1)*DD + col0] = make_float2(cB[2]*i1, cB[3]*i1);
    }
}

// ---------------------------------------------------------------------------
extern "C" void kernel_launch(void* const* d_in, const int* in_sizes, int n_in,
                              void* d_out, int out_size)
{
    const float* q     = (const float*)d_in[0];
    const float* k     = (const float*)d_in[1];
    const float* v     = (const float*)d_in[2];
    const float* omega = (const float*)d_in[3];
    float* out = (float*)d_out;

    cudaFuncSetAttribute(phi_sum_kernel,
                         cudaFuncAttributeMaxDynamicSharedMemorySize, PHI_SMEM_BYTES);

    phi_sum_kernel<<<BH*16, 256, PHI_SMEM_BYTES>>>(q, k, v, omega);
    const int scan_threads = BH*MM*8 + BH*MM;
    scan_kernel<<<(scan_threads + 255)/256, 256>>>();
    out_kernel<<<BH*CC, 256>>>(v, out);
}

// round 16
// speedup vs baseline: 1.6768x; 1.1137x over previous
#include <cuda_runtime.h>

#define BH 16
#define NSEQ 2048
#define DD 32
#define MM 64
#define LL 32
#define CC (NSEQ/LL)   // 64 chunks

typedef unsigned long long u64;

// packed f32x2 helpers
__device__ __forceinline__ u64 pk2(float x, float y) {
    u64 r; asm("mov.b64 %0, {%1, %2};" : "=l"(r) : "f"(x), "f"(y)); return r;
}
__device__ __forceinline__ void fma2(u64& d, u64 a, u64 b) {
    asm("fma.rn.f32x2 %0, %1, %2, %0;" : "+l"(d) : "l"(a), "l"(b));
}
__device__ __forceinline__ float2 up2(u64 a) {
    float2 f; asm("mov.b64 {%0, %1}, %2;" : "=f"(f.x), "=f"(f.y) : "l"(a)); return f;
}

// tf32 helpers
__device__ __forceinline__ unsigned cvt_tf32(float x) {
    unsigned r; asm("cvt.rna.tf32.f32 %0, %1;" : "=r"(r) : "f"(x)); return r;
}
__device__ __forceinline__ void mma_tf32(float* c, const unsigned* a, const unsigned* b) {
    asm("mma.sync.aligned.m16n8k8.row.col.f32.tf32.tf32.f32 "
        "{%0,%1,%2,%3}, {%4,%5,%6,%7}, {%8,%9}, {%0,%1,%2,%3};"
        : "+f"(c[0]), "+f"(c[1]), "+f"(c[2]), "+f"(c[3])
        : "r"(a[0]), "r"(a[1]), "r"(a[2]), "r"(a[3]), "r"(b[0]), "r"(b[1]));
}

// FMA-pipe exp: exp(x) = 2^(x*log2e); magic-round + deg-5 poly + exponent splice.
// Avoids MUFU (rt_SMSP=8 made 4M exps a ~16us chip floor). Rel err ~2e-6.
__device__ __forceinline__ float fast_exp(float x) {
    float y  = x * 1.4426950408889634f;
    float t  = y + 12582912.0f;              // 1.5 * 2^23
    int   i  = __float_as_int(t);
    float f  = y - (t - 12582912.0f);        // f in [-0.5, 0.5]
    float p  = 0.00133335581f;
    p = fmaf(p, f, 0.00961812910f);
    p = fmaf(p, f, 0.0555041087f);
    p = fmaf(p, f, 0.240226507f);
    p = fmaf(p, f, 0.693147181f);
    p = fmaf(p, f, 1.0f);
    float s  = __int_as_float((i << 23) + 0x3f800000);
    return p * s;
}

#define LN_SQRT_M 2.0794415416798357f   // ln(8): folds the 1/sqrt(64) factor

// Scratch (device globals)
__device__ float g_phi_q[BH*NSEQ*MM];     // 8 MB
__device__ float g_phi_k[BH*NSEQ*MM];     // 8 MB
__device__ float g_skv[BH*CC*MM*DD];      // 8 MB
__device__ float g_sk [BH*CC*MM];         // 256 KB

// phi kernel smem offsets
#define OFF_OM   0          // 32 x 72 tf32 bits (mma phase)
#define OFF_XQ   2304       // 128 x 36 fp32
#define OFF_XK   6912
#define OFF_PKS  0          // 128 x 72 phi_k (overlays OM/XQ after projections)
#define OFF_VS   9216       // 128 x 40 v (stride 40 for MMA B-frags)
#define OFF_NQ   14336
#define OFF_NK   14464
#define PHI_SMEM_FLOATS 14592
#define PHI_SMEM_BYTES  (PHI_SMEM_FLOATS*4)   // 58368

// ---------------------------------------------------------------------------
// Kernel 1: tf32 MMA projections + poly exp + tf32 MMA chunk sums.
// ---------------------------------------------------------------------------
__global__ void __launch_bounds__(256, 2) phi_sum_kernel(
    const float* __restrict__ q, const float* __restrict__ k,
    const float* __restrict__ v, const float* __restrict__ omega)
{
    extern __shared__ float smem[];
    float* om_t = smem + OFF_OM;
    float* xq   = smem + OFF_XQ;
    float* xk   = smem + OFF_XK;
    float* pk_s = smem + OFF_PKS;
    float* vs   = smem + OFF_VS;
    float* nq_s = smem + OFF_NQ;
    float* nk_s = smem + OFF_NK;

    int tid = threadIdx.x;
    int blk = blockIdx.x;
    int bh  = blk >> 4;
    int cq  = blk & 15;
    int base_tok = bh*NSEQ + cq*128;

    {
        int m = tid & 63;
        int d0 = (tid >> 6) * 8;
        #pragma unroll
        for (int jj = 0; jj < 8; jj++) {
            int d = d0 + jj;
            ((unsigned*)om_t)[d*72 + m] = cvt_tf32(omega[m*DD + d]);
        }
    }
    {
        const float4* q4 = (const float4*)(q + base_tok*DD);
        const float4* k4 = (const float4*)(k + base_tok*DD);
        #pragma unroll
        for (int r = 0; r < 4; r++) {
            int idx = tid + r*256;
            int t = idx >> 3, j = idx & 7;
            *(float4*)(xq + t*36 + j*4) = q4[idx];
            *(float4*)(xk + t*36 + j*4) = k4[idx];
        }
    }
    __syncthreads();

    // full-fp32 norms
    {
        int t = tid & 127;
        const float* src = (tid < 128) ? (xq + t*36) : (xk + t*36);
        float n = 0.f;
        #pragma unroll
        for (int j = 0; j < 8; j++) {
            float4 xv = *(const float4*)(src + j*4);
            n += xv.x*xv.x + xv.y*xv.y + xv.z*xv.z + xv.w*xv.w;
        }
        n = n*0.5f + LN_SQRT_M;
        if (tid < 128) nq_s[t] = n; else nk_s[t] = n;
    }

    int w = tid >> 5, lane = tid & 31;
    int g = lane >> 2, i = lane & 3;
    int t0 = w * 16;
    float cq_[8][4] = {}, ck_[8][4] = {};
    {
        const unsigned* omb = (const unsigned*)om_t;
        #pragma unroll
        for (int ks = 0; ks < 4; ks++) {
            int k0 = ks*8;
            unsigned aq[4], ak[4];
            aq[0] = cvt_tf32(xq[(t0+g  )*36 + k0+i  ]);
            aq[1] = cvt_tf32(xq[(t0+g+8)*36 + k0+i  ]);
            aq[2] = cvt_tf32(xq[(t0+g  )*36 + k0+i+4]);
            aq[3] = cvt_tf32(xq[(t0+g+8)*36 + k0+i+4]);
            ak[0] = cvt_tf32(xk[(t0+g  )*36 + k0+i  ]);
            ak[1] = cvt_tf32(xk[(t0+g+8)*36 + k0+i  ]);
            ak[2] = cvt_tf32(xk[(t0+g  )*36 + k0+i+4]);
            ak[3] = cvt_tf32(xk[(t0+g+8)*36 + k0+i+4]);
            #pragma unroll
            for (int n = 0; n < 8; n++) {
                unsigned b[2];
                b[0] = omb[(k0+i  )*72 + n*8 + g];
                b[1] = omb[(k0+4+i)*72 + n*8 + g];
                mma_tf32(cq_[n], aq, b);
                mma_tf32(ck_[n], ak, b);
            }
        }
    }
    __syncthreads();

    // epilogue: poly exp + stores; also load v (stride 40)
    {
        int r0 = t0 + g, r1 = t0 + g + 8;
        float n_q0 = nq_s[r0], n_q1 = nq_s[r1];
        float n_k0 = nk_s[r0], n_k1 = nk_s[r1];
        #pragma unroll
        for (int n = 0; n < 8; n++) {
            int col = n*8 + 2*i;
            float2 pq0, pq1, pk0, pk1;
            pq0.x = fast_exp(cq_[n][0] - n_q0); pq0.y = fast_exp(cq_[n][1] - n_q0);
            pq1.x = fast_exp(cq_[n][2] - n_q1); pq1.y = fast_exp(cq_[n][3] - n_q1);
            pk0.x = fast_exp(ck_[n][0] - n_k0); pk0.y = fast_exp(ck_[n][1] - n_k0);
            pk1.x = fast_exp(ck_[n][2] - n_k1); pk1.y = fast_exp(ck_[n][3] - n_k1);
            *(float2*)&g_phi_q[(base_tok + r0)*MM + col] = pq0;
            *(float2*)&g_phi_q[(base_tok + r1)*MM + col] = pq1;
            *(float2*)&g_phi_k[(base_tok + r0)*MM + col] = pk0;
            *(float2*)&g_phi_k[(base_tok + r1)*MM + col] = pk1;
            *(float2*)&pk_s[r0*72 + col] = pk0;
            *(float2*)&pk_s[r1*72 + col] = pk1;
        }
        const float4* v4 = (const float4*)(v + base_tok*DD);
        #pragma unroll
        for (int r = 0; r < 4; r++) {
            int idx = tid + r*256;
            int t = idx >> 3, j = idx & 7;
            *(float4*)(vs + t*40 + j*4) = v4[idx];
        }
    }
    __syncthreads();

    // --- chunk sums via tf32 MMA: skv[m][d] = sum_t phi_k[t][m] * v[t][d] ---
    // warp w: chunk ch = w>>1, m-half mh = w&1 (M=32: tiles m0, m0+16); N=32.
    {
        int ch = w >> 1, mh = w & 1;
        int chb = ch * 32;              // token base within pk_s/vs
        int m0 = mh * 32;
        int r = lane >> 2, cp = lane & 3;
        float c[2][4][4] = {};          // [mt][ntd][4]
        #pragma unroll
        for (int ks = 0; ks < 4; ks++) {
            int k0 = ks*8;
            unsigned a[2][4];
            #pragma unroll
            for (int mt = 0; mt < 2; mt++) {
                int row0 = m0 + mt*16 + r;
                a[mt][0] = cvt_tf32(pk_s[(chb + k0+cp  )*72 + row0    ]);
                a[mt][1] = cvt_tf32(pk_s[(chb + k0+cp  )*72 + row0 + 8]);
                a[mt][2] = cvt_tf32(pk_s[(chb + k0+cp+4)*72 + row0    ]);
                a[mt][3] = cvt_tf32(pk_s[(chb + k0+cp+4)*72 + row0 + 8]);
            }
            #pragma unroll
            for (int nt = 0; nt < 4; nt++) {
                unsigned b[2];
                b[0] = cvt_tf32(vs[(chb + k0+cp  )*40 + nt*8 + r]);
                b[1] = cvt_tf32(vs[(chb + k0+cp+4)*40 + nt*8 + r]);
                mma_tf32(c[0][nt], a[0], b);
                mma_tf32(c[1][nt], a[1], b);
            }
        }
        int blkc = bh*CC + cq*4 + ch;
        #pragma unroll
        for (int mt = 0; mt < 2; mt++) {
            int row0 = m0 + mt*16 + r;
            #pragma unroll
            for (int nt = 0; nt < 4; nt++) {
                int col = nt*8 + 2*cp;
                *(float2*)&g_skv[(size_t)(blkc*MM + row0    )*DD + col] =
                    make_float2(c[mt][nt][0], c[mt][nt][1]);
                *(float2*)&g_skv[(size_t)(blkc*MM + row0 + 8)*DD + col] =
                    make_float2(c[mt][nt][2], c[mt][nt][3]);
            }
        }
    }
    // sk[m] = sum_t phi_k[t][m] (scalar; 64 threads per chunk)
    {
        int ch = tid >> 6;
        int m  = tid & 63;
        const float* pk = pk_s + ch*32*72;
        float ks = 0.f;
        #pragma unroll 8
        for (int t = 0; t < LL; t++) ks += pk[t*72 + m];
        int blkc = bh*CC + cq*4 + ch;
        g_sk[blkc*MM + m] = ks;
    }
}

// ---------------------------------------------------------------------------
// Kernel 2: exclusive prefix scan over chunks (in place), float4 for skv.
// ---------------------------------------------------------------------------
__global__ void scan_kernel()
{
    int idx = blockIdx.x * blockDim.x + threadIdx.x;
    const int NSKV = BH*MM*8;
    if (idx < NSKV) {
        int bh = idx / (MM*8);
        int r  = idx % (MM*8);
        float4* base = (float4*)g_skv + (size_t)bh*CC*MM*8 + r;
        float4 run = {0,0,0,0};
        #pragma unroll 4
        for (int c = 0; c < CC; c++) {
            float4 t = base[(size_t)c*MM*8];
            base[(size_t)c*MM*8] = run;
            run.x += t.x; run.y += t.y; run.z += t.z; run.w += t.w;
        }
    } else if (idx < NSKV + BH*MM) {
        int j  = idx - NSKV;
        int bh = j / MM, m = j % MM;
        float* base = g_sk + bh*CC*MM + m;
        float run = 0.f;
        #pragma unroll 4
        for (int c = 0; c < CC; c++) {
            float t = base[c*MM];
            base[c*MM] = run;
            run += t;
        }
    }
}

// ---------------------------------------------------------------------------
// Kernel 3 (R15 known-good): all-tf32-MMA output kernel.
// ---------------------------------------------------------------------------
__global__ void __launch_bounds__(256) out_kernel(
    const float* __restrict__ v, float* __restrict__ out)
{
    __shared__ float pq_p[LL*68];
    __shared__ float pk_p[LL*68];
    __shared__ float sp_s[MM*40];
    __shared__ float v_s [LL*40];
    __shared__ float A_s [LL*36];
    __shared__ float kp  [MM];
    __shared__ float s_qk[LL];
    __shared__ float den_part[4*LL];

    int tid = threadIdx.x;
    int blk = blockIdx.x;
    int base_tok = (blk/CC)*NSEQ + (blk%CC)*LL;

    {
        const float4* gq4 = (const float4*)&g_phi_q[base_tok*MM];
        const float4* gk4 = (const float4*)&g_phi_k[base_tok*MM];
        const float4* gs4 = (const float4*)&g_skv[(size_t)blk*MM*DD];
        const float4* gv4 = (const float4*)(v + base_tok*DD);
        #pragma unroll
        for (int r = 0; r < 2; r++) {
            int idx = tid + r*256;
            int i = idx >> 4, m4 = idx & 15;
            ((float4*)pq_p)[i*17 + m4] = gq4[idx];
            ((float4*)pk_p)[i*17 + m4] = gk4[idx];
            int m = idx >> 3, j = idx & 7;
            *(float4*)(sp_s + m*40 + j*4) = gs4[idx];
        }
        int t = tid >> 3, j = tid & 7;
        *(float4*)(v_s + t*40 + j*4) = gv4[tid];
        if (tid < MM) kp[tid] = g_sk[blk*MM + tid];
    }
    __syncthreads();

    int w = tid >> 5, lane = tid & 31;
    int mt = w & 1, nt = w >> 1;
    int r = lane >> 2, cp = lane & 3;
    int row0 = mt*16 + r, row1 = row0 + 8;

    {
        float cA[4] = {0,0,0,0};
        #pragma unroll
        for (int ks = 0; ks < 8; ks++) {
            int k0 = ks*8;
            unsigned a[4], b[2];
            a[0] = cvt_tf32(pq_p[row0*68 + k0 + cp    ]);
            a[1] = cvt_tf32(pq_p[row1*68 + k0 + cp    ]);
            a[2] = cvt_tf32(pq_p[row0*68 + k0 + cp + 4]);
            a[3] = cvt_tf32(pq_p[row1*68 + k0 + cp + 4]);
            b[0] = cvt_tf32(pk_p[(nt*8 + r)*68 + k0 + cp    ]);
            b[1] = cvt_tf32(pk_p[(nt*8 + r)*68 + k0 + cp + 4]);
            mma_tf32(cA, a, b);
        }
        int col0 = nt*8 + 2*cp, col1 = col0 + 1;
        float m00 = (col0 <= row0) ? cA[0] : 0.f;
        float m01 = (col1 <= row0) ? cA[1] : 0.f;
        float m10 = (col0 <= row1) ? cA[2] : 0.f;
        float m11 = (col1 <= row1) ? cA[3] : 0.f;
        *(float2*)&A_s[row0*36 + col0] = make_float2(m00, m01);
        *(float2*)&A_s[row1*36 + col0] = make_float2(m10, m11);
        float p0 = m00 + m01, p1 = m10 + m11;
        p0 += __shfl_xor_sync(0xffffffffu, p0, 1);
        p0 += __shfl_xor_sync(0xffffffffu, p0, 2);
        p1 += __shfl_xor_sync(0xffffffffu, p1, 1);
        p1 += __shfl_xor_sync(0xffffffffu, p1, 2);
        if (cp == 0) {
            den_part[nt*LL + row0] = p0;
            den_part[nt*LL + row1] = p1;
        }
        if (w == 0) {
            const ulonglong2* pqU = (const ulonglong2*)pq_p;
            const ulonglong2* kpU = (const ulonglong2*)kp;
            u64 QK = 0;
            #pragma unroll
            for (int m4 = 0; m4 < 16; m4++) {
                ulonglong2 qv = pqU[lane*17 + m4];
                ulonglong2 kv = kpU[m4];
                fma2(QK, qv.x, kv.x); fma2(QK, qv.y, kv.y);
            }
            float2 fq = up2(QK);
            s_qk[lane] = fq.x + fq.y + 1e-6f;
        }
    }
    __syncthreads();

    {
        float cB[4] = {0,0,0,0};
        #pragma unroll
        for (int ks = 0; ks < 8; ks++) {
            int k0 = ks*8;
            unsigned a[4], b[2];
            a[0] = cvt_tf32(pq_p[row0*68 + k0 + cp    ]);
            a[1] = cvt_tf32(pq_p[row1*68 + k0 + cp    ]);
            a[2] = cvt_tf32(pq_p[row0*68 + k0 + cp + 4]);
            a[3] = cvt_tf32(pq_p[row1*68 + k0 + cp + 4]);
            b[0] = cvt_tf32(sp_s[(k0 + cp    )*40 + nt*8 + r]);
            b[1] = cvt_tf32(sp_s[(k0 + cp + 4)*40 + nt*8 + r]);
            mma_tf32(cB, a, b);
        }
        #pragma unroll
        for (int ks = 0; ks < 4; ks++) {
            int k0 = ks*8;
            unsigned a[4], b[2];
            a[0] = cvt_tf32(A_s[row0*36 + k0 + cp    ]);
            a[1] = cvt_tf32(A_s[row1*36 + k0 + cp    ]);
            a[2] = cvt_tf32(A_s[row0*36 + k0 + cp + 4]);
            a[3] = cvt_tf32(A_s[row1*36 + k0 + cp + 4]);
            b[0] = cvt_tf32(v_s[(k0 + cp    )*40 + nt*8 + r]);
            b[1] = cvt_tf32(v_s[(k0 + cp + 4)*40 + nt*8 + r]);
            mma_tf32(cB, a, b);
        }
        float den0 = s_qk[row0] + den_part[row0]        + den_part[LL + row0]
                                + den_part[2*LL + row0] + den_part[3*LL + row0];
        float den1 = s_qk[row1] + den_part[row1]        + den_part[LL + row1]
                                + den_part[2*LL + row1] + den_part[3*LL + row1];
        float i0 = 1.0f / den0, i1 = 1.0f / den1;
        int col0 = nt*8 + 2*cp;
        *(float2*)&out[(base_tok + row0)*DD + col0] = make_float2(cB[0]*i0, cB[1]*i0);
        *(float2*)&out[(base_tok + row1)*DD + col0] = make_float2(cB[2]*i1, cB[3]*i1);
    }
}

// ---------------------------------------------------------------------------
extern "C" void kernel_launch(void* const* d_in, const int* in_sizes, int n_in,
                              void* d_out, int out_size)
{
    const float* q     = (const float*)d_in[0];
    const float* k     = (const float*)d_in[1];
    const float* v     = (const float*)d_in[2];
    const float* omega = (const float*)d_in[3];
    float* out = (float*)d_out;

    cudaFuncSetAttribute(phi_sum_kernel,
                         cudaFuncAttributeMaxDynamicSharedMemorySize, PHI_SMEM_BYTES);

    phi_sum_kernel<<<BH*16, 256, PHI_SMEM_BYTES>>>(q, k, v, omega);
    const int scan_threads = BH*MM*8 + BH*MM;
    scan_kernel<<<(scan_threads + 255)/256, 256>>>();
    out_kernel<<<BH*CC, 256>>>(v, out);
}

// round 17
// speedup vs baseline: 1.7771x; 1.0598x over previous
#include <cuda_runtime.h>

#define BH 16
#define NSEQ 2048
#define DD 32
#define MM 64
#define LL 32
#define CC (NSEQ/LL)   // 64 chunks
#define NBLK 256       // bh*16 + cq; each block = 4 chunks (128 tokens)

typedef unsigned long long u64;

// packed f32x2 helpers
__device__ __forceinline__ u64 pk2(float x, float y) {
    u64 r; asm("mov.b64 %0, {%1, %2};" : "=l"(r) : "f"(x), "f"(y)); return r;
}
__device__ __forceinline__ void fma2(u64& d, u64 a, u64 b) {
    asm("fma.rn.f32x2 %0, %1, %2, %0;" : "+l"(d) : "l"(a), "l"(b));
}
__device__ __forceinline__ float2 up2(u64 a) {
    float2 f; asm("mov.b64 {%0, %1}, %2;" : "=f"(f.x), "=f"(f.y) : "l"(a)); return f;
}

// tf32 helpers
__device__ __forceinline__ unsigned cvt_tf32(float x) {
    unsigned r; asm("cvt.rna.tf32.f32 %0, %1;" : "=r"(r) : "f"(x)); return r;
}
__device__ __forceinline__ void mma_tf32(float* c, const unsigned* a, const unsigned* b) {
    asm("mma.sync.aligned.m16n8k8.row.col.f32.tf32.tf32.f32 "
        "{%0,%1,%2,%3}, {%4,%5,%6,%7}, {%8,%9}, {%0,%1,%2,%3};"
        : "+f"(c[0]), "+f"(c[1]), "+f"(c[2]), "+f"(c[3])
        : "r"(a[0]), "r"(a[1]), "r"(a[2]), "r"(a[3]), "r"(b[0]), "r"(b[1]));
}

// FMA-pipe exp (R16 known-good): avoids the MUFU rt=8 floor. Rel err ~2e-6.
__device__ __forceinline__ float fast_exp(float x) {
    float y  = x * 1.4426950408889634f;
    float t  = y + 12582912.0f;              // 1.5 * 2^23
    int   i  = __float_as_int(t);
    float f  = y - (t - 12582912.0f);        // f in [-0.5, 0.5]
    float p  = 0.00133335581f;
    p = fmaf(p, f, 0.00961812910f);
    p = fmaf(p, f, 0.0555041087f);
    p = fmaf(p, f, 0.240226507f);
    p = fmaf(p, f, 0.693147181f);
    p = fmaf(p, f, 1.0f);
    float s  = __int_as_float((i << 23) + 0x3f800000);
    return p * s;
}

#define LN_SQRT_M 2.0794415416798357f

// Scratch (device globals) — phi no longer touches global memory
__device__ float g_skv[BH*CC*MM*DD];      // 8 MB: chunk sums -> exclusive prefix
__device__ float g_sk [BH*CC*MM];         // 256 KB
__device__ unsigned int g_bar_cnt = 0;    // grid barrier (epoch monotonic)
__device__ unsigned int g_bar_epoch = 0;

__device__ __forceinline__ void grid_barrier()
{
    __syncthreads();
    if (threadIdx.x == 0) {
        __threadfence();
        unsigned int e = *((volatile unsigned int*)&g_bar_epoch);
        unsigned int old = atomicAdd(&g_bar_cnt, 1);
        if (old == NBLK - 1) {
            g_bar_cnt = 0;
            __threadfence();
            *((volatile unsigned int*)&g_bar_epoch) = e + 1;
        } else {
            while (*((volatile unsigned int*)&g_bar_epoch) == e) { __nanosleep(64); }
        }
        __threadfence();
    }
    __syncthreads();
}

// smem float offsets. Region1 (om/xq/xk) is dead after the projection MMAs and
// is overlaid by pq_s + sp_s. Total 27488 floats = 107.4 KB -> 2 CTA/SM.
#define SM_OM   0        // 32 x 72 tf32 bits
#define SM_XQ   2304     // 128 x 36 fp32
#define SM_XK   6912     // 128 x 36
#define SM_PQ   0        // overlay: 128 x 68 phi_q
#define SM_SP   8704     // overlay: 64 x 40 Sp (per out-chunk)
#define SM_PK   11520    // 128 x 72 phi_k
#define SM_V    20736    // 128 x 40 v
#define SM_NQ   25856    // 128 norms
#define SM_NK   25984
#define SM_A    26112    // 32 x 36 A (per out-chunk)
#define SM_KP   27264    // 64
#define SM_QK   27328    // 32
#define SM_DEN  27360    // 4 x 32
#define FUSED_SMEM_FLOATS 27488
#define FUSED_SMEM_BYTES  (FUSED_SMEM_FLOATS*4)   // 109952

// ---------------------------------------------------------------------------
// ONE persistent kernel: phi(MMA) -> chunk sums(MMA) -> [bar] -> scan -> [bar]
// -> out(MMA) x4 chunks. phi_q/phi_k live in smem end-to-end.
// ---------------------------------------------------------------------------
__global__ void __launch_bounds__(256, 2) fused_kernel(
    const float* __restrict__ q, const float* __restrict__ k,
    const float* __restrict__ v, const float* __restrict__ omega,
    float* __restrict__ out)
{
    extern __shared__ float sm[];
    float* om_t = sm + SM_OM;
    float* xq   = sm + SM_XQ;
    float* xk   = sm + SM_XK;
    float* pq_s = sm + SM_PQ;     // stride 68 (4r+c bank-unique for A-frags)
    float* sp_s = sm + SM_SP;     // stride 40
    float* pk_s = sm + SM_PK;     // stride 72 (chunk-sum A-frags bank-unique)
    float* v_s  = sm + SM_V;      // stride 40
    float* nq_s = sm + SM_NQ;
    float* nk_s = sm + SM_NK;
    float* A_s  = sm + SM_A;      // stride 36
    float* kp   = sm + SM_KP;
    float* s_qk = sm + SM_QK;
    float* den_part = sm + SM_DEN;

    int tid = threadIdx.x;
    int blk = blockIdx.x;
    int bh  = blk >> 4;
    int cq  = blk & 15;
    int base_tok = bh*NSEQ + cq*128;

    // ---- load omega (tf32, [d][m] stride 72) + q/k (stride 36) ----
    {
        int m = tid & 63;
        int d0 = (tid >> 6) * 8;
        #pragma unroll
        for (int jj = 0; jj < 8; jj++) {
            int d = d0 + jj;
            ((unsigned*)om_t)[d*72 + m] = cvt_tf32(omega[m*DD + d]);
        }
        const float4* q4 = (const float4*)(q + base_tok*DD);
        const float4* k4 = (const float4*)(k + base_tok*DD);
        #pragma unroll
        for (int r = 0; r < 4; r++) {
            int idx = tid + r*256;
            int t = idx >> 3, j = idx & 7;
            *(float4*)(xq + t*36 + j*4) = q4[idx];
            *(float4*)(xk + t*36 + j*4) = k4[idx];
        }
    }
    __syncthreads();

    // ---- full-fp32 norms ----
    {
        int t = tid & 127;
        const float* src = (tid < 128) ? (xq + t*36) : (xk + t*36);
        float n = 0.f;
        #pragma unroll
        for (int j = 0; j < 8; j++) {
            float4 xv = *(const float4*)(src + j*4);
            n += xv.x*xv.x + xv.y*xv.y + xv.z*xv.z + xv.w*xv.w;
        }
        n = n*0.5f + LN_SQRT_M;
        if (tid < 128) nq_s[t] = n; else nk_s[t] = n;
    }

    // ---- projection MMAs (warp w = 16 tokens) ----
    int w = tid >> 5, lane = tid & 31;
    int g = lane >> 2, i = lane & 3;
    int t0w = w * 16;
    float cq_[8][4] = {}, ck_[8][4] = {};
    {
        const unsigned* omb = (const unsigned*)om_t;
        #pragma unroll
        for (int ks = 0; ks < 4; ks++) {
            int k0 = ks*8;
            unsigned aq[4], ak[4];
            aq[0] = cvt_tf32(xq[(t0w+g  )*36 + k0+i  ]);
            aq[1] = cvt_tf32(xq[(t0w+g+8)*36 + k0+i  ]);
            aq[2] = cvt_tf32(xq[(t0w+g  )*36 + k0+i+4]);
            aq[3] = cvt_tf32(xq[(t0w+g+8)*36 + k0+i+4]);
            ak[0] = cvt_tf32(xk[(t0w+g  )*36 + k0+i  ]);
            ak[1] = cvt_tf32(xk[(t0w+g+8)*36 + k0+i  ]);
            ak[2] = cvt_tf32(xk[(t0w+g  )*36 + k0+i+4]);
            ak[3] = cvt_tf32(xk[(t0w+g+8)*36 + k0+i+4]);
            #pragma unroll
            for (int n = 0; n < 8; n++) {
                unsigned b[2];
                b[0] = omb[(k0+i  )*72 + n*8 + g];
                b[1] = omb[(k0+4+i)*72 + n*8 + g];
                mma_tf32(cq_[n], aq, b);
                mma_tf32(ck_[n], ak, b);
            }
        }
    }
    __syncthreads();   // om/xq/xk reads done; overlay becomes safe; norms visible

    // ---- epilogue: poly exp -> pq_s (stride 68) + pk_s (stride 72); load v ----
    {
        int r0 = t0w + g, r1 = t0w + g + 8;
        float n_q0 = nq_s[r0], n_q1 = nq_s[r1];
        float n_k0 = nk_s[r0], n_k1 = nk_s[r1];
        #pragma unroll
        for (int n = 0; n < 8; n++) {
            int col = n*8 + 2*i;
            float2 pq0, pq1, pk0, pk1;
            pq0.x = fast_exp(cq_[n][0] - n_q0); pq0.y = fast_exp(cq_[n][1] - n_q0);
            pq1.x = fast_exp(cq_[n][2] - n_q1); pq1.y = fast_exp(cq_[n][3] - n_q1);
            pk0.x = fast_exp(ck_[n][0] - n_k0); pk0.y = fast_exp(ck_[n][1] - n_k0);
            pk1.x = fast_exp(ck_[n][2] - n_k1); pk1.y = fast_exp(ck_[n][3] - n_k1);
            *(float2*)&pq_s[r0*68 + col] = pq0;
            *(float2*)&pq_s[r1*68 + col] = pq1;
            *(float2*)&pk_s[r0*72 + col] = pk0;
            *(float2*)&pk_s[r1*72 + col] = pk1;
        }
        const float4* v4 = (const float4*)(v + base_tok*DD);
        #pragma unroll
        for (int r = 0; r < 4; r++) {
            int idx = tid + r*256;
            int t = idx >> 3, j = idx & 7;
            *(float4*)(v_s + t*40 + j*4) = v4[idx];
        }
    }
    __syncthreads();

    // ---- chunk sums via tf32 MMA -> g_skv; sk scalar -> g_sk ----
    {
        int ch = w >> 1, mh = w & 1;
        int chb = ch * 32;
        int m0 = mh * 32;
        int r = lane >> 2, cp = lane & 3;
        float c[2][4][4] = {};
        #pragma unroll
        for (int ks = 0; ks < 4; ks++) {
            int k0 = ks*8;
            unsigned a[2][4];
            #pragma unroll
            for (int mt = 0; mt < 2; mt++) {
                int row0 = m0 + mt*16 + r;
                a[mt][0] = cvt_tf32(pk_s[(chb + k0+cp  )*72 + row0    ]);
                a[mt][1] = cvt_tf32(pk_s[(chb + k0+cp  )*72 + row0 + 8]);
                a[mt][2] = cvt_tf32(pk_s[(chb + k0+cp+4)*72 + row0    ]);
                a[mt][3] = cvt_tf32(pk_s[(chb + k0+cp+4)*72 + row0 + 8]);
            }
            #pragma unroll
            for (int nt = 0; nt < 4; nt++) {
                unsigned b[2];
                b[0] = cvt_tf32(v_s[(chb + k0+cp  )*40 + nt*8 + r]);
                b[1] = cvt_tf32(v_s[(chb + k0+cp+4)*40 + nt*8 + r]);
                mma_tf32(c[0][nt], a[0], b);
                mma_tf32(c[1][nt], a[1], b);
            }
        }
        int blkc = bh*CC + cq*4 + ch;
        #pragma unroll
        for (int mt = 0; mt < 2; mt++) {
            int row0 = m0 + mt*16 + r;
            #pragma unroll
            for (int nt = 0; nt < 4; nt++) {
                int col = nt*8 + 2*cp;
                *(float2*)&g_skv[(size_t)(blkc*MM + row0    )*DD + col] =
                    make_float2(c[mt][nt][0], c[mt][nt][1]);
                *(float2*)&g_skv[(size_t)(blkc*MM + row0 + 8)*DD + col] =
                    make_float2(c[mt][nt][2], c[mt][nt][3]);
            }
        }
    }
    {
        int ch = tid >> 6;
        int m  = tid & 63;
        const float* pk = pk_s + ch*32*72;
        float ks = 0.f;
        #pragma unroll 8
        for (int t = 0; t < LL; t++) ks += pk[t*72 + m];
        g_sk[(bh*CC + cq*4 + ch)*MM + m] = ks;
    }

    grid_barrier();

    // ---- scan (blocks 0..35 exactly cover 9216 series) ----
    {
        int idx = blk*256 + tid;
        const int NSKV = BH*MM*8;
        if (idx < NSKV) {
            int sbh = idx / (MM*8);
            int r   = idx % (MM*8);
            float4* base = (float4*)g_skv + (size_t)sbh*CC*MM*8 + r;
            float4 run = {0,0,0,0};
            #pragma unroll 8
            for (int c = 0; c < CC; c++) {
                float4 t = base[(size_t)c*MM*8];
                base[(size_t)c*MM*8] = run;
                run.x += t.x; run.y += t.y; run.z += t.z; run.w += t.w;
            }
        } else if (idx < NSKV + BH*MM) {
            int j   = idx - NSKV;
            int sbh = j / MM, m = j % MM;
            float* base = g_sk + sbh*CC*MM + m;
            float run = 0.f;
            #pragma unroll 8
            for (int c = 0; c < CC; c++) {
                float t = base[c*MM];
                base[c*MM] = run;
                run += t;
            }
        }
    }

    grid_barrier();

    // ---- output: 4 chunks sequentially, all tf32 MMA ----
    int mt = w & 1, nt = w >> 1;
    int r = lane >> 2, cp = lane & 3;
    int lrow0 = mt*16 + r, lrow1 = lrow0 + 8;   // local rows in chunk

    #pragma unroll 1
    for (int ch = 0; ch < 4; ch++) {
        int blkc = bh*CC + cq*4 + ch;
        int chb = ch*32;

        // load Sp (64x32 -> stride 40) + kp
        {
            const float4* gs4 = (const float4*)&g_skv[(size_t)blkc*MM*DD];
            #pragma unroll
            for (int rr = 0; rr < 2; rr++) {
                int idx = tid + rr*256;
                int m = idx >> 3, j = idx & 7;
                *(float4*)(sp_s + m*40 + j*4) = gs4[idx];
            }
            if (tid < MM) kp[tid] = g_sk[blkc*MM + tid];
        }
        __syncthreads();

        // Phase A: A = phi_q phi_k^T (masked) + den partials + warp0 qk
        {
            float cA[4] = {0,0,0,0};
            #pragma unroll
            for (int ks = 0; ks < 8; ks++) {
                int k0 = ks*8;
                unsigned a[4], b[2];
                a[0] = cvt_tf32(pq_s[(chb+lrow0)*68 + k0 + cp    ]);
                a[1] = cvt_tf32(pq_s[(chb+lrow1)*68 + k0 + cp    ]);
                a[2] = cvt_tf32(pq_s[(chb+lrow0)*68 + k0 + cp + 4]);
                a[3] = cvt_tf32(pq_s[(chb+lrow1)*68 + k0 + cp + 4]);
                b[0] = cvt_tf32(pk_s[(chb + nt*8 + r)*72 + k0 + cp    ]);
                b[1] = cvt_tf32(pk_s[(chb + nt*8 + r)*72 + k0 + cp + 4]);
                mma_tf32(cA, a, b);
            }
            int col0 = nt*8 + 2*cp, col1 = col0 + 1;
            float m00 = (col0 <= lrow0) ? cA[0] : 0.f;
            float m01 = (col1 <= lrow0) ? cA[1] : 0.f;
            float m10 = (col0 <= lrow1) ? cA[2] : 0.f;
            float m11 = (col1 <= lrow1) ? cA[3] : 0.f;
            *(float2*)&A_s[lrow0*36 + col0] = make_float2(m00, m01);
            *(float2*)&A_s[lrow1*36 + col0] = make_float2(m10, m11);
            float p0 = m00 + m01, p1 = m10 + m11;
            p0 += __shfl_xor_sync(0xffffffffu, p0, 1);
            p0 += __shfl_xor_sync(0xffffffffu, p0, 2);
            p1 += __shfl_xor_sync(0xffffffffu, p1, 1);
            p1 += __shfl_xor_sync(0xffffffffu, p1, 2);
            if (cp == 0) {
                den_part[nt*LL + lrow0] = p0;
                den_part[nt*LL + lrow1] = p1;
            }
            if (w == 0) {
                const ulonglong2* pqU = (const ulonglong2*)pq_s;
                const ulonglong2* kpU = (const ulonglong2*)kp;
                u64 QK = 0;
                #pragma unroll
                for (int m4 = 0; m4 < 16; m4++) {
                    ulonglong2 qv = pqU[(chb + lane)*17 + m4];
                    ulonglong2 kv = kpU[m4];
                    fma2(QK, qv.x, kv.x); fma2(QK, qv.y, kv.y);
                }
                float2 fq = up2(QK);
                s_qk[lane] = fq.x + fq.y + 1e-6f;
            }
        }
        __syncthreads();

        // Phase B: out = phi_q@Sp + A@v, den inline
        {
            float cB[4] = {0,0,0,0};
            #pragma unroll
            for (int ks = 0; ks < 8; ks++) {
                int k0 = ks*8;
                unsigned a[4], b[2];
                a[0] = cvt_tf32(pq_s[(chb+lrow0)*68 + k0 + cp    ]);
                a[1] = cvt_tf32(pq_s[(chb+lrow1)*68 + k0 + cp    ]);
                a[2] = cvt_tf32(pq_s[(chb+lrow0)*68 + k0 + cp + 4]);
                a[3] = cvt_tf32(pq_s[(chb+lrow1)*68 + k0 + cp + 4]);
                b[0] = cvt_tf32(sp_s[(k0 + cp    )*40 + nt*8 + r]);
                b[1] = cvt_tf32(sp_s[(k0 + cp + 4)*40 + nt*8 + r]);
                mma_tf32(cB, a, b);
            }
            #pragma unroll
            for (int ks = 0; ks < 4; ks++) {
                int k0 = ks*8;
                unsigned a[4], b[2];
                a[0] = cvt_tf32(A_s[lrow0*36 + k0 + cp    ]);
                a[1] = cvt_tf32(A_s[lrow1*36 + k0 + cp    ]);
                a[2] = cvt_tf32(A_s[lrow0*36 + k0 + cp + 4]);
                a[3] = cvt_tf32(A_s[lrow1*36 + k0 + cp + 4]);
                b[0] = cvt_tf32(v_s[(chb + k0 + cp    )*40 + nt*8 + r]);
                b[1] = cvt_tf32(v_s[(chb + k0 + cp + 4)*40 + nt*8 + r]);
                mma_tf32(cB, a, b);
            }
            float den0 = s_qk[lrow0] + den_part[lrow0]        + den_part[LL + lrow0]
                                     + den_part[2*LL + lrow0] + den_part[3*LL + lrow0];
            float den1 = s_qk[lrow1] + den_part[lrow1]        + den_part[LL + lrow1]
                                     + den_part[2*LL + lrow1] + den_part[3*LL + lrow1];
            float i0 = 1.0f / den0, i1 = 1.0f / den1;
            int col0 = nt*8 + 2*cp;
            *(float2*)&out[(base_tok + chb + lrow0)*DD + col0] =
                make_float2(cB[0]*i0, cB[1]*i0);
            *(float2*)&out[(base_tok + chb + lrow1)*DD + col0] =
                make_float2(cB[2]*i1, cB[3]*i1);
        }
        __syncthreads();   // A_s/sp_s/kp reused next chunk
    }
}

// ---------------------------------------------------------------------------
extern "C" void kernel_launch(void* const* d_in, const int* in_sizes, int n_in,
                              void* d_out, int out_size)
{
    const float* q     = (const float*)d_in[0];
    const float* k     = (const float*)d_in[1];
    const float* v     = (const float*)d_in[2];
    const float* omega = (const float*)d_in[3];
    float* out = (float*)d_out;

    cudaFuncSetAttribute(fused_kernel,
                         cudaFuncAttributeMaxDynamicSharedMemorySize, FUSED_SMEM_BYTES);

    fused_kernel<<<NBLK, 256, FUSED_SMEM_BYTES>>>(q, k, v, omega, out);
}